// round 13
// baseline (speedup 1.0000x reference)
#include <cuda_runtime.h>
#include <cuda_fp16.h>
#include <math.h>

#define BB 4
#define TT 1024
#define DD 1024
#define HH 16
#define DHH 64
#define DCC 64
#define BT (BB*TT)        // 4096
#define BTD (BB*TT*DD)    // 4194304
#define BIAS_ELEMS (HH*TT*TT) // 16777216

// ---------------- scratch (device globals; no allocation) ----------------
__device__ float g_gamma1[BB*DD];
__device__ float g_beta1 [BB*DD];
__device__ float g_gamma3[BB*DD];
__device__ float g_beta3 [BB*DD];
__device__ float g_x1  [BTD];
__device__ float g_biasrel[HH*2048];
// fp16 activation/weight buffers
__device__ __half g_y_h  [BTD];
__device__ __half g_qkv_h[(size_t)BT*3*DD];   // packed q|k|v per row
__device__ __half g_ctx_h[BTD];
__device__ __half g_gg_h [(size_t)BT*2*DD];
__device__ __half g_wqkvT[(size_t)3*DD*DD];   // q rows 0-1023, k 1024-2047, v 2048-3071
__device__ __half g_woT[DD*DD];
__device__ __half g_w1T[(size_t)4*DD*DD];     // geglu-permuted rows
__device__ __half g_w2T[(size_t)2*DD*DD];

__device__ __forceinline__ unsigned smem_u32(const void* p) {
    return (unsigned)__cvta_generic_to_shared(p);
}

// ---------------- FiLM params ----------------
__global__ void film_params_kernel(const float* __restrict__ cond,
    const float* __restrict__ g1w, const float* __restrict__ g1b,
    const float* __restrict__ b1w, const float* __restrict__ b1b,
    const float* __restrict__ g3w, const float* __restrict__ g3b,
    const float* __restrict__ b3w, const float* __restrict__ b3b)
{
    int idx = blockIdx.x * blockDim.x + threadIdx.x;
    if (idx >= BB*DD) return;
    int b = idx / DD, d = idx % DD;
    float s1 = 0.f, s2 = 0.f, s3 = 0.f, s4 = 0.f;
    #pragma unroll 8
    for (int c = 0; c < DCC; c++) {
        float cv = cond[b*DCC + c];
        s1 += cv * g1w[c*DD + d];
        s2 += cv * b1w[c*DD + d];
        s3 += cv * g3w[c*DD + d];
        s4 += cv * b3w[c*DD + d];
    }
    g_gamma1[idx] = s1 + g1b[d];
    g_beta1 [idx] = s2 + b1b[d];
    g_gamma3[idx] = s3 + g3b[d];
    g_beta3 [idx] = s4 + b3b[d];
}

// ---------------- T5 bucket ----------------
__device__ __forceinline__ int t5_bucket(int rp) {
    int bucket = (rp > 0) ? 16 : 0;
    int arp = rp < 0 ? -rp : rp;
    int off;
    if (arp < 8) {
        off = arp;
    } else {
        float l = logf((float)arp * 0.125f) / logf(16.0f) * 8.0f;
        off = 8 + (int)l;
        if (off > 15) off = 15;
    }
    return bucket + off;
}

__global__ void biasrel_kernel(const float* __restrict__ rel_emb)
{
    int idx = blockIdx.x * blockDim.x + threadIdx.x;
    if (idx >= 2047) return;
    int bucket = t5_bucket(idx - 1023);
    #pragma unroll
    for (int h = 0; h < HH; h++)
        g_biasrel[h*2048 + idx] = rel_emb[bucket*HH + h];
}

__global__ void bias_out_kernel(const float* __restrict__ rel_emb, float* __restrict__ outbias)
{
    int idx = blockIdx.x * blockDim.x + threadIdx.x;
    if (idx >= TT*TT) return;
    int q = idx / TT, k = idx % TT;
    int bucket = t5_bucket(k - q);
    #pragma unroll
    for (int h = 0; h < HH; h++)
        outbias[(size_t)h*TT*TT + idx] = rel_emb[bucket*HH + h];
}

// ---------------- weight transpose -> half K-major ----------------
// mode 0: dst[n][k] = src[k][n]
// mode 1: geglu permute: n<half -> 2n ; n>=half -> 2(n-half)+1   (half = Nd/2)
__global__ void transpose_h_kernel(const float* __restrict__ src, __half* __restrict__ dst,
                                   int Kd, int Nd, int mode)
{
    __shared__ float ts[32][33];
    int n0 = blockIdx.x*32, k0 = blockIdx.y*32;
    int tx = threadIdx.x, ty = threadIdx.y;   // 32 x 8
    #pragma unroll
    for (int i = 0; i < 32; i += 8)
        ts[ty+i][tx] = src[(size_t)(k0+ty+i)*Nd + n0+tx];
    __syncthreads();
    int half = Nd >> 1;
    #pragma unroll
    for (int i = 0; i < 32; i += 8) {
        int n = n0 + ty + i;
        int nd = (mode == 1) ? ((n < half) ? 2*n : 2*(n - half) + 1) : n;
        dst[(size_t)nd*Kd + k0+tx] = __float2half_rn(ts[tx][ty+i]);
    }
}

// ---------------- RMSNorm + FiLM (float4 in, half out) ----------------
__global__ void rmsnorm_film_kernel(const float* __restrict__ x, const float* __restrict__ w,
                                    const float* __restrict__ gamma, const float* __restrict__ beta,
                                    __half* __restrict__ y)
{
    int row = blockIdx.x;
    int b = row / TT;
    const float* xr = x + (size_t)row * DD;
    __half* yr = y + (size_t)row * DD;
    int d4 = threadIdx.x * 4;
    float4 v = *reinterpret_cast<const float4*>(&xr[d4]);
    float s = v.x*v.x + v.y*v.y + v.z*v.z + v.w*v.w;
    __shared__ float red[256];
    red[threadIdx.x] = s; __syncthreads();
    for (int o = 128; o > 0; o >>= 1) {
        if (threadIdx.x < o) red[threadIdx.x] += red[threadIdx.x + o];
        __syncthreads();
    }
    float rs = rsqrtf(red[0] * (1.0f/DD) + 1e-6f);
    float4 wv = *reinterpret_cast<const float4*>(&w[d4]);
    float4 gv = *reinterpret_cast<const float4*>(&gamma[b*DD + d4]);
    float4 bv = *reinterpret_cast<const float4*>(&beta[b*DD + d4]);
    __half2 h0 = __floats2half2_rn(wv.x * v.x * rs * (gv.x + 1.0f) + bv.x,
                                   wv.y * v.y * rs * (gv.y + 1.0f) + bv.y);
    __half2 h1 = __floats2half2_rn(wv.z * v.z * rs * (gv.z + 1.0f) + bv.z,
                                   wv.w * v.w * rs * (gv.w + 1.0f) + bv.w);
    *reinterpret_cast<__half2*>(&yr[d4])   = h0;
    *reinterpret_cast<__half2*>(&yr[d4+2]) = h1;
}

// ---------------- FP16 tensor-core GEMM, both operands K-major half ----------------
// out_mode 0: C fp32 (+Res) ; 1: Ch half ; 2: Ch half geglu (N/2 cols, permuted w)
#define GBM 128
#define GBN 128
#define GBK 32
#define HPAD 8

__global__ __launch_bounds__(256) void gemm_f16_kernel(int M, int N, int K,
    const __half* __restrict__ A, const __half* __restrict__ Bt,
    const float* __restrict__ Res, float* __restrict__ C, __half* __restrict__ Ch,
    int out_mode)
{
    __shared__ __half As[2][GBM][GBK+HPAD];
    __shared__ __half Bs[2][GBN][GBK+HPAD];

    int tid = threadIdx.x;
    int wid = tid >> 5, lane = tid & 31;
    int wm = wid >> 2, wn = wid & 3;

    const __half* Ag = A  + (size_t)blockIdx.y * GBM * K;
    const __half* Bg = Bt + (size_t)blockIdx.x * GBN * K;

    float acc[4][4][4];
    #pragma unroll
    for (int i = 0; i < 4; i++)
        #pragma unroll
        for (int j = 0; j < 4; j++)
            #pragma unroll
            for (int r = 0; r < 4; r++) acc[i][j][r] = 0.f;

    int lr = tid >> 2, lc = (tid & 3) * 8;

    #define LOAD_STAGE(buf, kt) do { \
        asm volatile("cp.async.cg.shared.global [%0], [%1], 16;\n" \
            :: "r"(smem_u32(&As[buf][lr][lc])),    "l"(Ag + (size_t)lr*K + (kt) + lc)); \
        asm volatile("cp.async.cg.shared.global [%0], [%1], 16;\n" \
            :: "r"(smem_u32(&As[buf][lr+64][lc])), "l"(Ag + (size_t)(lr+64)*K + (kt) + lc)); \
        asm volatile("cp.async.cg.shared.global [%0], [%1], 16;\n" \
            :: "r"(smem_u32(&Bs[buf][lr][lc])),    "l"(Bg + (size_t)lr*K + (kt) + lc)); \
        asm volatile("cp.async.cg.shared.global [%0], [%1], 16;\n" \
            :: "r"(smem_u32(&Bs[buf][lr+64][lc])), "l"(Bg + (size_t)(lr+64)*K + (kt) + lc)); \
        asm volatile("cp.async.commit_group;\n"); \
    } while (0)

    int nk = K / GBK;
    LOAD_STAGE(0, 0);

    for (int t = 0; t < nk; t++) {
        if (t + 1 < nk) LOAD_STAGE((t+1) & 1, (t+1) * GBK);
        else            asm volatile("cp.async.commit_group;\n");
        asm volatile("cp.async.wait_group 1;\n");
        __syncthreads();

        int buf = t & 1;
        #pragma unroll
        for (int kk = 0; kk < 2; kk++) {
            int k0 = kk * 16;
            int kc = k0 + (lane >> 4) * 8;
            unsigned af[4][4];
            unsigned bf[2][4];
            #pragma unroll
            for (int i = 0; i < 4; i++) {
                int m = wm*64 + i*16 + (lane & 15);
                asm volatile("ldmatrix.sync.aligned.m8n8.x4.shared.b16 {%0,%1,%2,%3}, [%4];\n"
                    : "=r"(af[i][0]), "=r"(af[i][1]), "=r"(af[i][2]), "=r"(af[i][3])
                    : "r"(smem_u32(&As[buf][m][kc])));
            }
            #pragma unroll
            for (int jb = 0; jb < 2; jb++) {
                int n = wn*32 + jb*16 + (lane & 15);
                asm volatile("ldmatrix.sync.aligned.m8n8.x4.shared.b16 {%0,%1,%2,%3}, [%4];\n"
                    : "=r"(bf[jb][0]), "=r"(bf[jb][1]), "=r"(bf[jb][2]), "=r"(bf[jb][3])
                    : "r"(smem_u32(&Bs[buf][n][kc])));
            }
            #pragma unroll
            for (int i = 0; i < 4; i++)
                #pragma unroll
                for (int j = 0; j < 4; j++) {
                    int jb = j >> 1, p = j & 1;
                    asm volatile(
                        "mma.sync.aligned.m16n8k16.row.col.f32.f16.f16.f32 "
                        "{%0,%1,%2,%3}, {%4,%5,%6,%7}, {%8,%9}, {%0,%1,%2,%3};\n"
                        : "+f"(acc[i][j][0]), "+f"(acc[i][j][1]), "+f"(acc[i][j][2]), "+f"(acc[i][j][3])
                        : "r"(af[i][0]), "r"(af[i][1]), "r"(af[i][2]), "r"(af[i][3]),
                          "r"(bf[jb][p]), "r"(bf[jb][p+2]));
                }
        }
        __syncthreads();
    }
    #undef LOAD_STAGE

    if (out_mode == 2) {
        // geglu epilogue: even col = p1, odd col = p2 (permuted w1T); emit half p1*gelu(p2)
        int Ng = N >> 1;
        __half* Cg = Ch + (size_t)blockIdx.y * GBM * Ng + blockIdx.x * (GBN >> 1);
        #pragma unroll
        for (int i = 0; i < 4; i++) {
            int r0 = wm*64 + i*16 + (lane >> 2);
            int r1 = r0 + 8;
            #pragma unroll
            for (int j = 0; j < 4; j++) {
                int gc = (wn*32 + j*8 + (lane & 3) * 2) >> 1;
                float p1a = acc[i][j][0], p2a = acc[i][j][1];
                float p1b = acc[i][j][2], p2b = acc[i][j][3];
                float ga = 0.5f * p2a * (1.0f + erff(p2a * 0.70710678118654752f));
                float gb = 0.5f * p2b * (1.0f + erff(p2b * 0.70710678118654752f));
                Cg[(size_t)r0*Ng + gc] = __float2half_rn(p1a * ga);
                Cg[(size_t)r1*Ng + gc] = __float2half_rn(p1b * gb);
            }
        }
    } else if (out_mode == 1) {
        __half* Cg = Ch + (size_t)blockIdx.y * GBM * N + blockIdx.x * GBN;
        #pragma unroll
        for (int i = 0; i < 4; i++) {
            int r0 = wm*64 + i*16 + (lane >> 2);
            int r1 = r0 + 8;
            #pragma unroll
            for (int j = 0; j < 4; j++) {
                int c0 = wn*32 + j*8 + (lane & 3) * 2;
                *reinterpret_cast<__half2*>(&Cg[(size_t)r0*N + c0]) =
                    __floats2half2_rn(acc[i][j][0], acc[i][j][1]);
                *reinterpret_cast<__half2*>(&Cg[(size_t)r1*N + c0]) =
                    __floats2half2_rn(acc[i][j][2], acc[i][j][3]);
            }
        }
    } else {
        float* Cg = C + (size_t)blockIdx.y * GBM * N + blockIdx.x * GBN;
        const float* Rg = Res ? Res + (size_t)blockIdx.y * GBM * N + blockIdx.x * GBN : nullptr;
        #pragma unroll
        for (int i = 0; i < 4; i++) {
            int r0 = wm*64 + i*16 + (lane >> 2);
            int r1 = r0 + 8;
            #pragma unroll
            for (int j = 0; j < 4; j++) {
                int c0 = wn*32 + j*8 + (lane & 3) * 2;
                float v0 = acc[i][j][0], v1 = acc[i][j][1];
                float v2 = acc[i][j][2], v3 = acc[i][j][3];
                if (Rg) {
                    v0 += Rg[(size_t)r0*N + c0];   v1 += Rg[(size_t)r0*N + c0+1];
                    v2 += Rg[(size_t)r1*N + c0];   v3 += Rg[(size_t)r1*N + c0+1];
                }
                Cg[(size_t)r0*N + c0]   = v0;  Cg[(size_t)r0*N + c0+1] = v1;
                Cg[(size_t)r1*N + c0]   = v2;  Cg[(size_t)r1*N + c0+1] = v3;
            }
        }
    }
}

// ---------------- fused flash attention (fp16 mma k16, packed qkv) ----------------
#define FPITCH 72
#define QKVD (3*DD)

struct FlashSmemH {
    __half Qh[64][FPITCH];
    __half Kh[64][FPITCH];
    __half Vh[64][FPITCH];
    __half Ph[4][16][FPITCH];
    float  Sb[128];
};

__global__ __launch_bounds__(128) void flash_attn_kernel(const int* __restrict__ mask)
{
    __shared__ FlashSmemH S;

    int qt = blockIdx.x, bh = blockIdx.y;
    int b = bh / HH, h = bh % HH;
    int q0 = qt * 64;
    int tid = threadIdx.x, wid = tid >> 5, lane = tid & 31;
    int lq = lane >> 2, lk = lane & 3;
    int qrel = wid*16 + lq;

    const __half2 qscale = __floats2half2_rn(0.125f, 0.125f);
    for (int i = tid; i < 64*16; i += 128) {
        int r = i >> 4, c4 = (i & 15) * 4;
        size_t off = (size_t)(b*TT + q0 + r)*QKVD + h*DHH + c4;
        __half2 a0 = *reinterpret_cast<const __half2*>(&g_qkv_h[off]);
        __half2 a1 = *reinterpret_cast<const __half2*>(&g_qkv_h[off+2]);
        *reinterpret_cast<__half2*>(&S.Qh[r][c4])   = __hmul2(a0, qscale);
        *reinterpret_cast<__half2*>(&S.Qh[r][c4+2]) = __hmul2(a1, qscale);
    }

    float o[8][4];
    #pragma unroll
    for (int n = 0; n < 8; n++)
        #pragma unroll
        for (int r = 0; r < 4; r++) o[n][r] = 0.f;
    float mrow[2] = { -3.0e38f, -3.0e38f };
    float lrow[2] = { 0.f, 0.f };

    for (int kt0 = 0; kt0 < TT; kt0 += 64) {
        __syncthreads();
        for (int i = tid; i < 64*16; i += 128) {
            int r = i >> 4, c4 = (i & 15) * 4;
            size_t off = (size_t)(b*TT + kt0 + r)*QKVD + h*DHH + c4;
            *reinterpret_cast<uint2*>(&S.Kh[r][c4]) =
                *reinterpret_cast<const uint2*>(&g_qkv_h[off + DD]);
            *reinterpret_cast<uint2*>(&S.Vh[r][c4]) =
                *reinterpret_cast<const uint2*>(&g_qkv_h[off + 2*DD]);
        }
        if (tid < 127) S.Sb[tid] = g_biasrel[h*2048 + (kt0 - q0 + 960) + tid];
        __syncthreads();

        float sacc[8][4];
        #pragma unroll
        for (int n = 0; n < 8; n++)
            #pragma unroll
            for (int r = 0; r < 4; r++) sacc[n][r] = 0.f;

        #pragma unroll
        for (int ks = 0; ks < 4; ks++) {
            int kc = ks*16 + (lane >> 4) * 8;
            unsigned aq[4];
            asm volatile("ldmatrix.sync.aligned.m8n8.x4.shared.b16 {%0,%1,%2,%3}, [%4];\n"
                : "=r"(aq[0]), "=r"(aq[1]), "=r"(aq[2]), "=r"(aq[3])
                : "r"(smem_u32(&S.Qh[wid*16 + (lane & 15)][kc])));
            unsigned bk[4][4];
            #pragma unroll
            for (int jb = 0; jb < 4; jb++) {
                asm volatile("ldmatrix.sync.aligned.m8n8.x4.shared.b16 {%0,%1,%2,%3}, [%4];\n"
                    : "=r"(bk[jb][0]), "=r"(bk[jb][1]), "=r"(bk[jb][2]), "=r"(bk[jb][3])
                    : "r"(smem_u32(&S.Kh[jb*16 + (lane & 15)][kc])));
            }
            #pragma unroll
            for (int n8 = 0; n8 < 8; n8++) {
                int jb = n8 >> 1, p = n8 & 1;
                asm volatile(
                    "mma.sync.aligned.m16n8k16.row.col.f32.f16.f16.f32 "
                    "{%0,%1,%2,%3}, {%4,%5,%6,%7}, {%8,%9}, {%0,%1,%2,%3};\n"
                    : "+f"(sacc[n8][0]), "+f"(sacc[n8][1]), "+f"(sacc[n8][2]), "+f"(sacc[n8][3])
                    : "r"(aq[0]), "r"(aq[1]), "r"(aq[2]), "r"(aq[3]),
                      "r"(bk[jb][p]), "r"(bk[jb][p+2]));
            }
        }

        float mnew[2] = { mrow[0], mrow[1] };
        #pragma unroll
        for (int n = 0; n < 8; n++) {
            #pragma unroll
            for (int e = 0; e < 2; e++) {
                int qr = qrel + e*8;
                const int* mrowp = mask + ((size_t)(b*TT + q0 + qr))*TT + kt0;
                #pragma unroll
                for (int c = 0; c < 2; c++) {
                    int kr = n*8 + 2*lk + c;
                    float s = sacc[n][e*2+c] + S.Sb[kr - qr + 63];
                    if (mrowp[kr] == 0) s = -1e9f;
                    sacc[n][e*2+c] = s;
                    mnew[e] = fmaxf(mnew[e], s);
                }
            }
        }
        #pragma unroll
        for (int e = 0; e < 2; e++) {
            mnew[e] = fmaxf(mnew[e], __shfl_xor_sync(0xffffffffu, mnew[e], 1));
            mnew[e] = fmaxf(mnew[e], __shfl_xor_sync(0xffffffffu, mnew[e], 2));
        }
        float alpha[2], rs[2] = {0.f, 0.f};
        alpha[0] = __expf(mrow[0] - mnew[0]);
        alpha[1] = __expf(mrow[1] - mnew[1]);
        mrow[0] = mnew[0]; mrow[1] = mnew[1];

        #pragma unroll
        for (int n = 0; n < 8; n++) {
            #pragma unroll
            for (int e = 0; e < 2; e++) {
                float p0 = __expf(sacc[n][e*2+0] - mnew[e]);
                float p1 = __expf(sacc[n][e*2+1] - mnew[e]);
                rs[e] += p0 + p1;
                *reinterpret_cast<__half2*>(&S.Ph[wid][lq + e*8][n*8 + 2*lk]) =
                    __floats2half2_rn(p0, p1);
            }
        }
        #pragma unroll
        for (int e = 0; e < 2; e++) {
            rs[e] += __shfl_xor_sync(0xffffffffu, rs[e], 1);
            rs[e] += __shfl_xor_sync(0xffffffffu, rs[e], 2);
            lrow[e] = lrow[e] * alpha[e] + rs[e];
        }
        #pragma unroll
        for (int n = 0; n < 8; n++) {
            o[n][0] *= alpha[0]; o[n][1] *= alpha[0];
            o[n][2] *= alpha[1]; o[n][3] *= alpha[1];
        }
        __syncwarp();

        #pragma unroll
        for (int ks = 0; ks < 4; ks++) {
            int kc = ks*16 + (lane >> 4) * 8;
            unsigned ap[4];
            asm volatile("ldmatrix.sync.aligned.m8n8.x4.shared.b16 {%0,%1,%2,%3}, [%4];\n"
                : "=r"(ap[0]), "=r"(ap[1]), "=r"(ap[2]), "=r"(ap[3])
                : "r"(smem_u32(&S.Ph[wid][lane & 15][kc])));
            int vrow = ks*16 + (lane & 7) + ((lane >> 3) & 1) * 8;
            unsigned bv[4][4];
            #pragma unroll
            for (int jb = 0; jb < 4; jb++) {
                int vcol = jb*16 + ((lane >> 4) & 1) * 8;
                asm volatile("ldmatrix.sync.aligned.m8n8.x4.trans.shared.b16 {%0,%1,%2,%3}, [%4];\n"
                    : "=r"(bv[jb][0]), "=r"(bv[jb][1]), "=r"(bv[jb][2]), "=r"(bv[jb][3])
                    : "r"(smem_u32(&S.Vh[vrow][vcol])));
            }
            #pragma unroll
            for (int n8 = 0; n8 < 8; n8++) {
                int jb = n8 >> 1, q2 = n8 & 1;
                asm volatile(
                    "mma.sync.aligned.m16n8k16.row.col.f32.f16.f16.f32 "
                    "{%0,%1,%2,%3}, {%4,%5,%6,%7}, {%8,%9}, {%0,%1,%2,%3};\n"
                    : "+f"(o[n8][0]), "+f"(o[n8][1]), "+f"(o[n8][2]), "+f"(o[n8][3])
                    : "r"(ap[0]), "r"(ap[1]), "r"(ap[2]), "r"(ap[3]),
                      "r"(bv[jb][2*q2]), "r"(bv[jb][2*q2+1]));
            }
        }
        __syncwarp();
    }

    float inv0 = 1.0f / lrow[0], inv1 = 1.0f / lrow[1];
    #pragma unroll
    for (int e = 0; e < 2; e++) {
        int qg = b*TT + q0 + qrel + e*8;
        float inv = e ? inv1 : inv0;
        #pragma unroll
        for (int n = 0; n < 8; n++) {
            __half2 hw = __floats2half2_rn(o[n][e*2+0] * inv, o[n][e*2+1] * inv);
            *reinterpret_cast<__half2*>(&g_ctx_h[(size_t)qg*DD + h*DHH + n*8 + 2*lk]) = hw;
        }
    }
}

// ---------------- host launcher ----------------
extern "C" void kernel_launch(void* const* d_in, const int* in_sizes, int n_in,
                              void* d_out, int out_size)
{
    const float* x       = (const float*)d_in[0];
    const int*   mask    = (const int*)  d_in[1];
    const float* cond    = (const float*)d_in[2];
    const float* norm1_w = (const float*)d_in[3];
    const float* f1gw    = (const float*)d_in[4];
    const float* f1gb    = (const float*)d_in[5];
    const float* f1bw    = (const float*)d_in[6];
    const float* f1bb    = (const float*)d_in[7];
    const float* wq      = (const float*)d_in[8];
    const float* wk      = (const float*)d_in[9];
    const float* wv      = (const float*)d_in[10];
    const float* wo      = (const float*)d_in[11];
    const float* rel_emb = (const float*)d_in[12];
    const float* norm3_w = (const float*)d_in[13];
    const float* f3gw    = (const float*)d_in[14];
    const float* f3gb    = (const float*)d_in[15];
    const float* f3bw    = (const float*)d_in[16];
    const float* f3bb    = (const float*)d_in[17];
    const float* w1      = (const float*)d_in[18];
    const float* w2      = (const float*)d_in[19];
    float* out = (float*)d_out;
    float* outbias = (out_size >= BTD + BIAS_ELEMS) ? out + BTD : nullptr;

    float *p_x1;
    float *p_g1, *p_b1, *p_g3, *p_b3;
    __half *p_y_h, *p_qkv_h, *p_ctx_h, *p_gg_h;
    __half *p_wqkvT, *p_woT, *p_w1T, *p_w2T;
    cudaGetSymbolAddress((void**)&p_g1, g_gamma1);
    cudaGetSymbolAddress((void**)&p_b1, g_beta1);
    cudaGetSymbolAddress((void**)&p_g3, g_gamma3);
    cudaGetSymbolAddress((void**)&p_b3, g_beta3);
    cudaGetSymbolAddress((void**)&p_x1, g_x1);
    cudaGetSymbolAddress((void**)&p_y_h,  g_y_h);
    cudaGetSymbolAddress((void**)&p_qkv_h, g_qkv_h);
    cudaGetSymbolAddress((void**)&p_ctx_h, g_ctx_h);
    cudaGetSymbolAddress((void**)&p_gg_h, g_gg_h);
    cudaGetSymbolAddress((void**)&p_wqkvT, g_wqkvT);
    cudaGetSymbolAddress((void**)&p_woT, g_woT);
    cudaGetSymbolAddress((void**)&p_w1T, g_w1T);
    cudaGetSymbolAddress((void**)&p_w2T, g_w2T);

    // 0) transpose weights -> half K-major (qkv packed; w1 geglu-permuted)
    dim3 tb(32, 8);
    transpose_h_kernel<<<dim3(DD/32, DD/32), tb>>>(wq, p_wqkvT,          DD, DD, 0);
    transpose_h_kernel<<<dim3(DD/32, DD/32), tb>>>(wk, p_wqkvT + DD*DD,  DD, DD, 0);
    transpose_h_kernel<<<dim3(DD/32, DD/32), tb>>>(wv, p_wqkvT + 2*DD*DD, DD, DD, 0);
    transpose_h_kernel<<<dim3(DD/32, DD/32), tb>>>(wo, p_woT, DD, DD, 0);
    transpose_h_kernel<<<dim3(4*DD/32, DD/32), tb>>>(w1, p_w1T, DD, 4*DD, 1);
    transpose_h_kernel<<<dim3(DD/32, 2*DD/32), tb>>>(w2, p_w2T, 2*DD, DD, 0);

    // 1) FiLM params + bias LUT + bias output
    film_params_kernel<<<(BB*DD + 255)/256, 256>>>(cond, f1gw, f1gb, f1bw, f1bb,
                                                   f3gw, f3gb, f3bw, f3bb);
    biasrel_kernel<<<(2047 + 255)/256, 256>>>(rel_emb);
    if (outbias)
        bias_out_kernel<<<(TT*TT + 255)/256, 256>>>(rel_emb, outbias);

    // 2) y = film(rmsnorm(x)) -> half
    rmsnorm_film_kernel<<<BT, 256>>>(x, norm1_w, p_g1, p_b1, p_y_h);

    // 3) merged QKV projection (fp16 MMA, half packed output)
    gemm_f16_kernel<<<dim3(3*DD/GBN, BT/GBM), 256>>>(BT, 3*DD, DD, p_y_h, p_wqkvT,
                                                     nullptr, nullptr, p_qkv_h, 1);

    // 4) fused flash attention (fp16) -> half ctx
    flash_attn_kernel<<<dim3(TT/64, BB*HH), 128>>>(mask);

    // 5) output projection + residual -> x1 (fp32)
    gemm_f16_kernel<<<dim3(DD/GBN, BT/GBM), 256>>>(BT, DD, DD, p_ctx_h, p_woT,
                                                   x, p_x1, nullptr, 0);

    // 6) y2 = film3(rmsnorm(x1)) -> half
    rmsnorm_film_kernel<<<BT, 256>>>(p_x1, norm3_w, p_g3, p_b3, p_y_h);

    // 7) FFN: fused ffn1+geglu -> half gg ; ffn2 + residual -> out
    gemm_f16_kernel<<<dim3(4*DD/GBN, BT/GBM), 256>>>(BT, 4*DD, DD, p_y_h, p_w1T,
                                                     nullptr, nullptr, p_gg_h, 2);
    gemm_f16_kernel<<<dim3(DD/GBN, BT/GBM), 256>>>(BT, DD, 2*DD, p_gg_h, p_w2T,
                                                   p_x1, out, nullptr, 0);
}

// round 14
// speedup vs baseline: 1.0639x; 1.0639x over previous
#include <cuda_runtime.h>
#include <cuda_fp16.h>
#include <math.h>

#define BB 4
#define TT 1024
#define DD 1024
#define HH 16
#define DHH 64
#define DCC 64
#define BT (BB*TT)        // 4096
#define BTD (BB*TT*DD)    // 4194304
#define BIAS_ELEMS (HH*TT*TT) // 16777216

// ---------------- scratch (device globals; no allocation) ----------------
__device__ float g_gamma1[BB*DD];
__device__ float g_beta1 [BB*DD];
__device__ float g_gamma3[BB*DD];
__device__ float g_beta3 [BB*DD];
__device__ float g_x1  [BTD];
__device__ float g_biasrel[HH*2048];
// fp16 activation/weight buffers
__device__ __half g_y_h  [BTD];
__device__ __half g_qkv_h[(size_t)BT*3*DD];   // packed q|k|v per row
__device__ __half g_ctx_h[BTD];
__device__ __half g_gg_h [(size_t)BT*2*DD];
__device__ __half g_wqkvT[(size_t)3*DD*DD];
__device__ __half g_woT[DD*DD];
__device__ __half g_w1T[(size_t)4*DD*DD];     // geglu-permuted rows
__device__ __half g_w2T[(size_t)2*DD*DD];

__device__ __forceinline__ unsigned smem_u32(const void* p) {
    return (unsigned)__cvta_generic_to_shared(p);
}

// ---------------- FiLM params ----------------
__global__ void film_params_kernel(const float* __restrict__ cond,
    const float* __restrict__ g1w, const float* __restrict__ g1b,
    const float* __restrict__ b1w, const float* __restrict__ b1b,
    const float* __restrict__ g3w, const float* __restrict__ g3b,
    const float* __restrict__ b3w, const float* __restrict__ b3b)
{
    int idx = blockIdx.x * blockDim.x + threadIdx.x;
    if (idx >= BB*DD) return;
    int b = idx / DD, d = idx % DD;
    float s1 = 0.f, s2 = 0.f, s3 = 0.f, s4 = 0.f;
    #pragma unroll 8
    for (int c = 0; c < DCC; c++) {
        float cv = cond[b*DCC + c];
        s1 += cv * g1w[c*DD + d];
        s2 += cv * b1w[c*DD + d];
        s3 += cv * g3w[c*DD + d];
        s4 += cv * b3w[c*DD + d];
    }
    g_gamma1[idx] = s1 + g1b[d];
    g_beta1 [idx] = s2 + b1b[d];
    g_gamma3[idx] = s3 + g3b[d];
    g_beta3 [idx] = s4 + b3b[d];
}

// ---------------- T5 bucket ----------------
__device__ __forceinline__ int t5_bucket(int rp) {
    int bucket = (rp > 0) ? 16 : 0;
    int arp = rp < 0 ? -rp : rp;
    int off;
    if (arp < 8) {
        off = arp;
    } else {
        float l = logf((float)arp * 0.125f) / logf(16.0f) * 8.0f;
        off = 8 + (int)l;
        if (off > 15) off = 15;
    }
    return bucket + off;
}

__global__ void biasrel_kernel(const float* __restrict__ rel_emb)
{
    int idx = blockIdx.x * blockDim.x + threadIdx.x;
    if (idx >= 2047) return;
    int bucket = t5_bucket(idx - 1023);
    #pragma unroll
    for (int h = 0; h < HH; h++)
        g_biasrel[h*2048 + idx] = rel_emb[bucket*HH + h];
}

__global__ void bias_out_kernel(const float* __restrict__ rel_emb, float* __restrict__ outbias)
{
    int idx = blockIdx.x * blockDim.x + threadIdx.x;
    if (idx >= TT*TT) return;
    int q = idx / TT, k = idx % TT;
    int bucket = t5_bucket(k - q);
    #pragma unroll
    for (int h = 0; h < HH; h++)
        outbias[(size_t)h*TT*TT + idx] = rel_emb[bucket*HH + h];
}

// ---------------- weight transpose -> half K-major ----------------
// mode 0: dst[n][k] = src[k][n]
// mode 1: geglu permute: n<half -> 2n ; n>=half -> 2(n-half)+1
__global__ void transpose_h_kernel(const float* __restrict__ src, __half* __restrict__ dst,
                                   int Kd, int Nd, int mode)
{
    __shared__ float ts[32][33];
    int n0 = blockIdx.x*32, k0 = blockIdx.y*32;
    int tx = threadIdx.x, ty = threadIdx.y;   // 32 x 8
    #pragma unroll
    for (int i = 0; i < 32; i += 8)
        ts[ty+i][tx] = src[(size_t)(k0+ty+i)*Nd + n0+tx];
    __syncthreads();
    int half = Nd >> 1;
    #pragma unroll
    for (int i = 0; i < 32; i += 8) {
        int n = n0 + ty + i;
        int nd = (mode == 1) ? ((n < half) ? 2*n : 2*(n - half) + 1) : n;
        dst[(size_t)nd*Kd + k0+tx] = __float2half_rn(ts[tx][ty+i]);
    }
}

// ---------------- RMSNorm + FiLM (float4 in, half out) ----------------
__global__ void rmsnorm_film_kernel(const float* __restrict__ x, const float* __restrict__ w,
                                    const float* __restrict__ gamma, const float* __restrict__ beta,
                                    __half* __restrict__ y)
{
    int row = blockIdx.x;
    int b = row / TT;
    const float* xr = x + (size_t)row * DD;
    __half* yr = y + (size_t)row * DD;
    int d4 = threadIdx.x * 4;
    float4 v = *reinterpret_cast<const float4*>(&xr[d4]);
    float s = v.x*v.x + v.y*v.y + v.z*v.z + v.w*v.w;
    __shared__ float red[256];
    red[threadIdx.x] = s; __syncthreads();
    for (int o = 128; o > 0; o >>= 1) {
        if (threadIdx.x < o) red[threadIdx.x] += red[threadIdx.x + o];
        __syncthreads();
    }
    float rs = rsqrtf(red[0] * (1.0f/DD) + 1e-6f);
    float4 wv = *reinterpret_cast<const float4*>(&w[d4]);
    float4 gv = *reinterpret_cast<const float4*>(&gamma[b*DD + d4]);
    float4 bv = *reinterpret_cast<const float4*>(&beta[b*DD + d4]);
    __half2 h0 = __floats2half2_rn(wv.x * v.x * rs * (gv.x + 1.0f) + bv.x,
                                   wv.y * v.y * rs * (gv.y + 1.0f) + bv.y);
    __half2 h1 = __floats2half2_rn(wv.z * v.z * rs * (gv.z + 1.0f) + bv.z,
                                   wv.w * v.w * rs * (gv.w + 1.0f) + bv.w);
    *reinterpret_cast<__half2*>(&yr[d4])   = h0;
    *reinterpret_cast<__half2*>(&yr[d4+2]) = h1;
}

// ---------------- FP16 tensor-core GEMM (templated epilogue -> separate reg alloc) ----------------
// OUT_MODE 0: C fp32 (+Res) ; 1: Ch half ; 2: Ch half geglu (N/2 cols, permuted w)
#define GBM 128
#define GBN 128
#define GBK 32
#define HPAD 8

template<int OUT_MODE>
__global__ __launch_bounds__(256) void gemm_f16_kernel(int M, int N, int K,
    const __half* __restrict__ A, const __half* __restrict__ Bt,
    const float* __restrict__ Res, float* __restrict__ C, __half* __restrict__ Ch)
{
    __shared__ __half As[2][GBM][GBK+HPAD];
    __shared__ __half Bs[2][GBN][GBK+HPAD];

    int tid = threadIdx.x;
    int wid = tid >> 5, lane = tid & 31;
    int wm = wid >> 2, wn = wid & 3;

    const __half* Ag = A  + (size_t)blockIdx.y * GBM * K;
    const __half* Bg = Bt + (size_t)blockIdx.x * GBN * K;

    float acc[4][4][4];
    #pragma unroll
    for (int i = 0; i < 4; i++)
        #pragma unroll
        for (int j = 0; j < 4; j++)
            #pragma unroll
            for (int r = 0; r < 4; r++) acc[i][j][r] = 0.f;

    int lr = tid >> 2, lc = (tid & 3) * 8;

    #define LOAD_STAGE(buf, kt) do { \
        asm volatile("cp.async.cg.shared.global [%0], [%1], 16;\n" \
            :: "r"(smem_u32(&As[buf][lr][lc])),    "l"(Ag + (size_t)lr*K + (kt) + lc)); \
        asm volatile("cp.async.cg.shared.global [%0], [%1], 16;\n" \
            :: "r"(smem_u32(&As[buf][lr+64][lc])), "l"(Ag + (size_t)(lr+64)*K + (kt) + lc)); \
        asm volatile("cp.async.cg.shared.global [%0], [%1], 16;\n" \
            :: "r"(smem_u32(&Bs[buf][lr][lc])),    "l"(Bg + (size_t)lr*K + (kt) + lc)); \
        asm volatile("cp.async.cg.shared.global [%0], [%1], 16;\n" \
            :: "r"(smem_u32(&Bs[buf][lr+64][lc])), "l"(Bg + (size_t)(lr+64)*K + (kt) + lc)); \
        asm volatile("cp.async.commit_group;\n"); \
    } while (0)

    int nk = K / GBK;
    LOAD_STAGE(0, 0);

    for (int t = 0; t < nk; t++) {
        if (t + 1 < nk) LOAD_STAGE((t+1) & 1, (t+1) * GBK);
        else            asm volatile("cp.async.commit_group;\n");
        asm volatile("cp.async.wait_group 1;\n");
        __syncthreads();

        int buf = t & 1;
        #pragma unroll
        for (int kk = 0; kk < 2; kk++) {
            int k0 = kk * 16;
            int kc = k0 + (lane >> 4) * 8;
            unsigned af[4][4];
            unsigned bf[2][4];
            #pragma unroll
            for (int i = 0; i < 4; i++) {
                int m = wm*64 + i*16 + (lane & 15);
                asm volatile("ldmatrix.sync.aligned.m8n8.x4.shared.b16 {%0,%1,%2,%3}, [%4];\n"
                    : "=r"(af[i][0]), "=r"(af[i][1]), "=r"(af[i][2]), "=r"(af[i][3])
                    : "r"(smem_u32(&As[buf][m][kc])));
            }
            #pragma unroll
            for (int jb = 0; jb < 2; jb++) {
                int n = wn*32 + jb*16 + (lane & 15);
                asm volatile("ldmatrix.sync.aligned.m8n8.x4.shared.b16 {%0,%1,%2,%3}, [%4];\n"
                    : "=r"(bf[jb][0]), "=r"(bf[jb][1]), "=r"(bf[jb][2]), "=r"(bf[jb][3])
                    : "r"(smem_u32(&Bs[buf][n][kc])));
            }
            #pragma unroll
            for (int i = 0; i < 4; i++)
                #pragma unroll
                for (int j = 0; j < 4; j++) {
                    int jb = j >> 1, p = j & 1;
                    asm volatile(
                        "mma.sync.aligned.m16n8k16.row.col.f32.f16.f16.f32 "
                        "{%0,%1,%2,%3}, {%4,%5,%6,%7}, {%8,%9}, {%0,%1,%2,%3};\n"
                        : "+f"(acc[i][j][0]), "+f"(acc[i][j][1]), "+f"(acc[i][j][2]), "+f"(acc[i][j][3])
                        : "r"(af[i][0]), "r"(af[i][1]), "r"(af[i][2]), "r"(af[i][3]),
                          "r"(bf[jb][p]), "r"(bf[jb][p+2]));
                }
        }
        __syncthreads();
    }
    #undef LOAD_STAGE

    if (OUT_MODE == 2) {
        // geglu: even col = p1, odd col = p2; emit half p1*gelu(p2)
        int Ng = N >> 1;
        __half* Cg = Ch + (size_t)blockIdx.y * GBM * Ng + blockIdx.x * (GBN >> 1);
        #pragma unroll
        for (int i = 0; i < 4; i++) {
            int r0 = wm*64 + i*16 + (lane >> 2);
            int r1 = r0 + 8;
            #pragma unroll
            for (int j = 0; j < 4; j++) {
                int gc = (wn*32 + j*8 + (lane & 3) * 2) >> 1;
                float p1a = acc[i][j][0], p2a = acc[i][j][1];
                float p1b = acc[i][j][2], p2b = acc[i][j][3];
                float ga = 0.5f * p2a * (1.0f + erff(p2a * 0.70710678118654752f));
                float gb = 0.5f * p2b * (1.0f + erff(p2b * 0.70710678118654752f));
                Cg[(size_t)r0*Ng + gc] = __float2half_rn(p1a * ga);
                Cg[(size_t)r1*Ng + gc] = __float2half_rn(p1b * gb);
            }
        }
    } else if (OUT_MODE == 1) {
        __half* Cg = Ch + (size_t)blockIdx.y * GBM * N + blockIdx.x * GBN;
        #pragma unroll
        for (int i = 0; i < 4; i++) {
            int r0 = wm*64 + i*16 + (lane >> 2);
            int r1 = r0 + 8;
            #pragma unroll
            for (int j = 0; j < 4; j++) {
                int c0 = wn*32 + j*8 + (lane & 3) * 2;
                *reinterpret_cast<__half2*>(&Cg[(size_t)r0*N + c0]) =
                    __floats2half2_rn(acc[i][j][0], acc[i][j][1]);
                *reinterpret_cast<__half2*>(&Cg[(size_t)r1*N + c0]) =
                    __floats2half2_rn(acc[i][j][2], acc[i][j][3]);
            }
        }
    } else {
        float* Cg = C + (size_t)blockIdx.y * GBM * N + blockIdx.x * GBN;
        const float* Rg = Res ? Res + (size_t)blockIdx.y * GBM * N + blockIdx.x * GBN : nullptr;
        #pragma unroll
        for (int i = 0; i < 4; i++) {
            int r0 = wm*64 + i*16 + (lane >> 2);
            int r1 = r0 + 8;
            #pragma unroll
            for (int j = 0; j < 4; j++) {
                int c0 = wn*32 + j*8 + (lane & 3) * 2;
                float v0 = acc[i][j][0], v1 = acc[i][j][1];
                float v2 = acc[i][j][2], v3 = acc[i][j][3];
                if (Rg) {
                    v0 += Rg[(size_t)r0*N + c0];   v1 += Rg[(size_t)r0*N + c0+1];
                    v2 += Rg[(size_t)r1*N + c0];   v3 += Rg[(size_t)r1*N + c0+1];
                }
                Cg[(size_t)r0*N + c0]   = v0;  Cg[(size_t)r0*N + c0+1] = v1;
                Cg[(size_t)r1*N + c0]   = v2;  Cg[(size_t)r1*N + c0+1] = v3;
            }
        }
    }
}

// ---------------- fused flash attention (fp16 mma k16, packed qkv) ----------------
#define FPITCH 72
#define QKVD (3*DD)

struct FlashSmemH {
    __half Qh[64][FPITCH];
    __half Kh[64][FPITCH];
    __half Vh[64][FPITCH];
    __half Ph[4][16][FPITCH];
    float  Sb[128];
};

__global__ __launch_bounds__(128) void flash_attn_kernel(const int* __restrict__ mask)
{
    __shared__ FlashSmemH S;

    int qt = blockIdx.x, bh = blockIdx.y;
    int b = bh / HH, h = bh % HH;
    int q0 = qt * 64;
    int tid = threadIdx.x, wid = tid >> 5, lane = tid & 31;
    int lq = lane >> 2, lk = lane & 3;
    int qrel = wid*16 + lq;

    const __half2 qscale = __floats2half2_rn(0.125f, 0.125f);
    for (int i = tid; i < 64*16; i += 128) {
        int r = i >> 4, c4 = (i & 15) * 4;
        size_t off = (size_t)(b*TT + q0 + r)*QKVD + h*DHH + c4;
        __half2 a0 = *reinterpret_cast<const __half2*>(&g_qkv_h[off]);
        __half2 a1 = *reinterpret_cast<const __half2*>(&g_qkv_h[off+2]);
        *reinterpret_cast<__half2*>(&S.Qh[r][c4])   = __hmul2(a0, qscale);
        *reinterpret_cast<__half2*>(&S.Qh[r][c4+2]) = __hmul2(a1, qscale);
    }

    float o[8][4];
    #pragma unroll
    for (int n = 0; n < 8; n++)
        #pragma unroll
        for (int r = 0; r < 4; r++) o[n][r] = 0.f;
    float mrow[2] = { -3.0e38f, -3.0e38f };
    float lrow[2] = { 0.f, 0.f };

    for (int kt0 = 0; kt0 < TT; kt0 += 64) {
        __syncthreads();
        for (int i = tid; i < 64*16; i += 128) {
            int r = i >> 4, c4 = (i & 15) * 4;
            size_t off = (size_t)(b*TT + kt0 + r)*QKVD + h*DHH + c4;
            *reinterpret_cast<uint2*>(&S.Kh[r][c4]) =
                *reinterpret_cast<const uint2*>(&g_qkv_h[off + DD]);
            *reinterpret_cast<uint2*>(&S.Vh[r][c4]) =
                *reinterpret_cast<const uint2*>(&g_qkv_h[off + 2*DD]);
        }
        if (tid < 127) S.Sb[tid] = g_biasrel[h*2048 + (kt0 - q0 + 960) + tid];
        __syncthreads();

        float sacc[8][4];
        #pragma unroll
        for (int n = 0; n < 8; n++)
            #pragma unroll
            for (int r = 0; r < 4; r++) sacc[n][r] = 0.f;

        #pragma unroll
        for (int ks = 0; ks < 4; ks++) {
            int kc = ks*16 + (lane >> 4) * 8;
            unsigned aq[4];
            asm volatile("ldmatrix.sync.aligned.m8n8.x4.shared.b16 {%0,%1,%2,%3}, [%4];\n"
                : "=r"(aq[0]), "=r"(aq[1]), "=r"(aq[2]), "=r"(aq[3])
                : "r"(smem_u32(&S.Qh[wid*16 + (lane & 15)][kc])));
            unsigned bk[4][4];
            #pragma unroll
            for (int jb = 0; jb < 4; jb++) {
                asm volatile("ldmatrix.sync.aligned.m8n8.x4.shared.b16 {%0,%1,%2,%3}, [%4];\n"
                    : "=r"(bk[jb][0]), "=r"(bk[jb][1]), "=r"(bk[jb][2]), "=r"(bk[jb][3])
                    : "r"(smem_u32(&S.Kh[jb*16 + (lane & 15)][kc])));
            }
            #pragma unroll
            for (int n8 = 0; n8 < 8; n8++) {
                int jb = n8 >> 1, p = n8 & 1;
                asm volatile(
                    "mma.sync.aligned.m16n8k16.row.col.f32.f16.f16.f32 "
                    "{%0,%1,%2,%3}, {%4,%5,%6,%7}, {%8,%9}, {%0,%1,%2,%3};\n"
                    : "+f"(sacc[n8][0]), "+f"(sacc[n8][1]), "+f"(sacc[n8][2]), "+f"(sacc[n8][3])
                    : "r"(aq[0]), "r"(aq[1]), "r"(aq[2]), "r"(aq[3]),
                      "r"(bk[jb][p]), "r"(bk[jb][p+2]));
            }
        }

        float mnew[2] = { mrow[0], mrow[1] };
        #pragma unroll
        for (int n = 0; n < 8; n++) {
            #pragma unroll
            for (int e = 0; e < 2; e++) {
                int qr = qrel + e*8;
                const int* mrowp = mask + ((size_t)(b*TT + q0 + qr))*TT + kt0;
                #pragma unroll
                for (int c = 0; c < 2; c++) {
                    int kr = n*8 + 2*lk + c;
                    float s = sacc[n][e*2+c] + S.Sb[kr - qr + 63];
                    if (mrowp[kr] == 0) s = -1e9f;
                    sacc[n][e*2+c] = s;
                    mnew[e] = fmaxf(mnew[e], s);
                }
            }
        }
        #pragma unroll
        for (int e = 0; e < 2; e++) {
            mnew[e] = fmaxf(mnew[e], __shfl_xor_sync(0xffffffffu, mnew[e], 1));
            mnew[e] = fmaxf(mnew[e], __shfl_xor_sync(0xffffffffu, mnew[e], 2));
        }
        float alpha[2], rs[2] = {0.f, 0.f};
        alpha[0] = __expf(mrow[0] - mnew[0]);
        alpha[1] = __expf(mrow[1] - mnew[1]);
        mrow[0] = mnew[0]; mrow[1] = mnew[1];

        #pragma unroll
        for (int n = 0; n < 8; n++) {
            #pragma unroll
            for (int e = 0; e < 2; e++) {
                float p0 = __expf(sacc[n][e*2+0] - mnew[e]);
                float p1 = __expf(sacc[n][e*2+1] - mnew[e]);
                rs[e] += p0 + p1;
                *reinterpret_cast<__half2*>(&S.Ph[wid][lq + e*8][n*8 + 2*lk]) =
                    __floats2half2_rn(p0, p1);
            }
        }
        #pragma unroll
        for (int e = 0; e < 2; e++) {
            rs[e] += __shfl_xor_sync(0xffffffffu, rs[e], 1);
            rs[e] += __shfl_xor_sync(0xffffffffu, rs[e], 2);
            lrow[e] = lrow[e] * alpha[e] + rs[e];
        }
        #pragma unroll
        for (int n = 0; n < 8; n++) {
            o[n][0] *= alpha[0]; o[n][1] *= alpha[0];
            o[n][2] *= alpha[1]; o[n][3] *= alpha[1];
        }
        __syncwarp();

        #pragma unroll
        for (int ks = 0; ks < 4; ks++) {
            int kc = ks*16 + (lane >> 4) * 8;
            unsigned ap[4];
            asm volatile("ldmatrix.sync.aligned.m8n8.x4.shared.b16 {%0,%1,%2,%3}, [%4];\n"
                : "=r"(ap[0]), "=r"(ap[1]), "=r"(ap[2]), "=r"(ap[3])
                : "r"(smem_u32(&S.Ph[wid][lane & 15][kc])));
            int vrow = ks*16 + (lane & 7) + ((lane >> 3) & 1) * 8;
            unsigned bv[4][4];
            #pragma unroll
            for (int jb = 0; jb < 4; jb++) {
                int vcol = jb*16 + ((lane >> 4) & 1) * 8;
                asm volatile("ldmatrix.sync.aligned.m8n8.x4.trans.shared.b16 {%0,%1,%2,%3}, [%4];\n"
                    : "=r"(bv[jb][0]), "=r"(bv[jb][1]), "=r"(bv[jb][2]), "=r"(bv[jb][3])
                    : "r"(smem_u32(&S.Vh[vrow][vcol])));
            }
            #pragma unroll
            for (int n8 = 0; n8 < 8; n8++) {
                int jb = n8 >> 1, q2 = n8 & 1;
                asm volatile(
                    "mma.sync.aligned.m16n8k16.row.col.f32.f16.f16.f32 "
                    "{%0,%1,%2,%3}, {%4,%5,%6,%7}, {%8,%9}, {%0,%1,%2,%3};\n"
                    : "+f"(o[n8][0]), "+f"(o[n8][1]), "+f"(o[n8][2]), "+f"(o[n8][3])
                    : "r"(ap[0]), "r"(ap[1]), "r"(ap[2]), "r"(ap[3]),
                      "r"(bv[jb][2*q2]), "r"(bv[jb][2*q2+1]));
            }
        }
        __syncwarp();
    }

    float inv0 = 1.0f / lrow[0], inv1 = 1.0f / lrow[1];
    #pragma unroll
    for (int e = 0; e < 2; e++) {
        int qg = b*TT + q0 + qrel + e*8;
        float inv = e ? inv1 : inv0;
        #pragma unroll
        for (int n = 0; n < 8; n++) {
            __half2 hw = __floats2half2_rn(o[n][e*2+0] * inv, o[n][e*2+1] * inv);
            *reinterpret_cast<__half2*>(&g_ctx_h[(size_t)qg*DD + h*DHH + n*8 + 2*lk]) = hw;
        }
    }
}

// ---------------- host launcher ----------------
extern "C" void kernel_launch(void* const* d_in, const int* in_sizes, int n_in,
                              void* d_out, int out_size)
{
    const float* x       = (const float*)d_in[0];
    const int*   mask    = (const int*)  d_in[1];
    const float* cond    = (const float*)d_in[2];
    const float* norm1_w = (const float*)d_in[3];
    const float* f1gw    = (const float*)d_in[4];
    const float* f1gb    = (const float*)d_in[5];
    const float* f1bw    = (const float*)d_in[6];
    const float* f1bb    = (const float*)d_in[7];
    const float* wq      = (const float*)d_in[8];
    const float* wk      = (const float*)d_in[9];
    const float* wv      = (const float*)d_in[10];
    const float* wo      = (const float*)d_in[11];
    const float* rel_emb = (const float*)d_in[12];
    const float* norm3_w = (const float*)d_in[13];
    const float* f3gw    = (const float*)d_in[14];
    const float* f3gb    = (const float*)d_in[15];
    const float* f3bw    = (const float*)d_in[16];
    const float* f3bb    = (const float*)d_in[17];
    const float* w1      = (const float*)d_in[18];
    const float* w2      = (const float*)d_in[19];
    float* out = (float*)d_out;
    float* outbias = (out_size >= BTD + BIAS_ELEMS) ? out + BTD : nullptr;

    float *p_x1;
    float *p_g1, *p_b1, *p_g3, *p_b3;
    __half *p_y_h, *p_qkv_h, *p_ctx_h, *p_gg_h;
    __half *p_wqkvT, *p_woT, *p_w1T, *p_w2T;
    cudaGetSymbolAddress((void**)&p_g1, g_gamma1);
    cudaGetSymbolAddress((void**)&p_b1, g_beta1);
    cudaGetSymbolAddress((void**)&p_g3, g_gamma3);
    cudaGetSymbolAddress((void**)&p_b3, g_beta3);
    cudaGetSymbolAddress((void**)&p_x1, g_x1);
    cudaGetSymbolAddress((void**)&p_y_h,  g_y_h);
    cudaGetSymbolAddress((void**)&p_qkv_h, g_qkv_h);
    cudaGetSymbolAddress((void**)&p_ctx_h, g_ctx_h);
    cudaGetSymbolAddress((void**)&p_gg_h, g_gg_h);
    cudaGetSymbolAddress((void**)&p_wqkvT, g_wqkvT);
    cudaGetSymbolAddress((void**)&p_woT, g_woT);
    cudaGetSymbolAddress((void**)&p_w1T, g_w1T);
    cudaGetSymbolAddress((void**)&p_w2T, g_w2T);

    // 0) transpose weights -> half K-major (qkv packed; w1 geglu-permuted)
    dim3 tb(32, 8);
    transpose_h_kernel<<<dim3(DD/32, DD/32), tb>>>(wq, p_wqkvT,           DD, DD, 0);
    transpose_h_kernel<<<dim3(DD/32, DD/32), tb>>>(wk, p_wqkvT + DD*DD,   DD, DD, 0);
    transpose_h_kernel<<<dim3(DD/32, DD/32), tb>>>(wv, p_wqkvT + 2*DD*DD, DD, DD, 0);
    transpose_h_kernel<<<dim3(DD/32, DD/32), tb>>>(wo, p_woT, DD, DD, 0);
    transpose_h_kernel<<<dim3(4*DD/32, DD/32), tb>>>(w1, p_w1T, DD, 4*DD, 1);
    transpose_h_kernel<<<dim3(DD/32, 2*DD/32), tb>>>(w2, p_w2T, 2*DD, DD, 0);

    // 1) FiLM params + bias LUT + bias output
    film_params_kernel<<<(BB*DD + 255)/256, 256>>>(cond, f1gw, f1gb, f1bw, f1bb,
                                                   f3gw, f3gb, f3bw, f3bb);
    biasrel_kernel<<<(2047 + 255)/256, 256>>>(rel_emb);
    if (outbias)
        bias_out_kernel<<<(TT*TT + 255)/256, 256>>>(rel_emb, outbias);

    // 2) y = film(rmsnorm(x)) -> half
    rmsnorm_film_kernel<<<BT, 256>>>(x, norm1_w, p_g1, p_b1, p_y_h);

    // 3) merged QKV projection (half packed output)
    gemm_f16_kernel<1><<<dim3(3*DD/GBN, BT/GBM), 256>>>(BT, 3*DD, DD, p_y_h, p_wqkvT,
                                                        nullptr, nullptr, p_qkv_h);

    // 4) fused flash attention (fp16) -> half ctx
    flash_attn_kernel<<<dim3(TT/64, BB*HH), 128>>>(mask);

    // 5) output projection + residual -> x1 (fp32)
    gemm_f16_kernel<0><<<dim3(DD/GBN, BT/GBM), 256>>>(BT, DD, DD, p_ctx_h, p_woT,
                                                      x, p_x1, nullptr);

    // 6) y2 = film3(rmsnorm(x1)) -> half
    rmsnorm_film_kernel<<<BT, 256>>>(p_x1, norm3_w, p_g3, p_b3, p_y_h);

    // 7) FFN: fused ffn1+geglu -> half gg ; ffn2 + residual -> out
    gemm_f16_kernel<2><<<dim3(4*DD/GBN, BT/GBM), 256>>>(BT, 4*DD, DD, p_y_h, p_w1T,
                                                        nullptr, nullptr, p_gg_h);
    gemm_f16_kernel<0><<<dim3(DD/GBN, BT/GBM), 256>>>(BT, DD, 2*DD, p_gg_h, p_w2T,
                                                      p_x1, out, nullptr);
}

// round 15
// speedup vs baseline: 1.1892x; 1.1178x over previous
#include <cuda_runtime.h>
#include <cuda_fp16.h>
#include <math.h>

#define BB 4
#define TT 1024
#define DD 1024
#define HH 16
#define DHH 64
#define DCC 64
#define BT (BB*TT)        // 4096
#define BTD (BB*TT*DD)    // 4194304
#define BIAS_ELEMS (HH*TT*TT) // 16777216

// ---------------- scratch (device globals; no allocation) ----------------
__device__ float g_gamma1[BB*DD];
__device__ float g_beta1 [BB*DD];
__device__ float g_gamma3[BB*DD];
__device__ float g_beta3 [BB*DD];
__device__ float g_x1  [BTD];
__device__ float g_biasrel[HH*2048];
__device__ unsigned g_maskbits[BT*32];        // [row][word]: bit k = mask!=0
// fp16 activation/weight buffers
__device__ __half g_y_h  [BTD];
__device__ __half g_qkv_h[(size_t)BT*3*DD];
__device__ __half g_ctx_h[BTD];
__device__ __half g_gg_h [(size_t)BT*2*DD];
__device__ __half g_wqkvT[(size_t)3*DD*DD];
__device__ __half g_woT[DD*DD];
__device__ __half g_w1T[(size_t)4*DD*DD];     // geglu-permuted rows
__device__ __half g_w2T[(size_t)2*DD*DD];

__device__ __forceinline__ unsigned smem_u32(const void* p) {
    return (unsigned)__cvta_generic_to_shared(p);
}

// ---------------- FiLM params ----------------
__global__ void film_params_kernel(const float* __restrict__ cond,
    const float* __restrict__ g1w, const float* __restrict__ g1b,
    const float* __restrict__ b1w, const float* __restrict__ b1b,
    const float* __restrict__ g3w, const float* __restrict__ g3b,
    const float* __restrict__ b3w, const float* __restrict__ b3b)
{
    int idx = blockIdx.x * blockDim.x + threadIdx.x;
    if (idx >= BB*DD) return;
    int b = idx / DD, d = idx % DD;
    float s1 = 0.f, s2 = 0.f, s3 = 0.f, s4 = 0.f;
    #pragma unroll 8
    for (int c = 0; c < DCC; c++) {
        float cv = cond[b*DCC + c];
        s1 += cv * g1w[c*DD + d];
        s2 += cv * b1w[c*DD + d];
        s3 += cv * g3w[c*DD + d];
        s4 += cv * b3w[c*DD + d];
    }
    g_gamma1[idx] = s1 + g1b[d];
    g_beta1 [idx] = s2 + b1b[d];
    g_gamma3[idx] = s3 + g3b[d];
    g_beta3 [idx] = s4 + b3b[d];
}

// ---------------- T5 bucket ----------------
__device__ __forceinline__ int t5_bucket(int rp) {
    int bucket = (rp > 0) ? 16 : 0;
    int arp = rp < 0 ? -rp : rp;
    int off;
    if (arp < 8) {
        off = arp;
    } else {
        float l = logf((float)arp * 0.125f) / logf(16.0f) * 8.0f;
        off = 8 + (int)l;
        if (off > 15) off = 15;
    }
    return bucket + off;
}

__global__ void biasrel_kernel(const float* __restrict__ rel_emb)
{
    int idx = blockIdx.x * blockDim.x + threadIdx.x;
    if (idx >= 2047) return;
    int bucket = t5_bucket(idx - 1023);
    #pragma unroll
    for (int h = 0; h < HH; h++)
        g_biasrel[h*2048 + idx] = rel_emb[bucket*HH + h];
}

__global__ void bias_out_kernel(const float* __restrict__ rel_emb, float* __restrict__ outbias)
{
    int idx = blockIdx.x * blockDim.x + threadIdx.x;
    if (idx >= TT*TT) return;
    int q = idx / TT, k = idx % TT;
    int bucket = t5_bucket(k - q);
    #pragma unroll
    for (int h = 0; h < HH; h++)
        outbias[(size_t)h*TT*TT + idx] = rel_emb[bucket*HH + h];
}

// ---------------- mask -> bitmask (one warp per row) ----------------
__global__ void maskbits_kernel(const int* __restrict__ mask)
{
    int warp = (blockIdx.x * blockDim.x + threadIdx.x) >> 5;
    int lane = threadIdx.x & 31;
    if (warp >= BT) return;
    const int* mrow = mask + (size_t)warp * TT;
    #pragma unroll 4
    for (int w = 0; w < 32; w++) {
        unsigned word = __ballot_sync(0xffffffffu, mrow[w*32 + lane] != 0);
        if (lane == 0) g_maskbits[warp*32 + w] = word;
    }
}

// ---------------- weight transpose -> half K-major ----------------
__global__ void transpose_h_kernel(const float* __restrict__ src, __half* __restrict__ dst,
                                   int Kd, int Nd, int mode)
{
    __shared__ float ts[32][33];
    int n0 = blockIdx.x*32, k0 = blockIdx.y*32;
    int tx = threadIdx.x, ty = threadIdx.y;   // 32 x 8
    #pragma unroll
    for (int i = 0; i < 32; i += 8)
        ts[ty+i][tx] = src[(size_t)(k0+ty+i)*Nd + n0+tx];
    __syncthreads();
    int half = Nd >> 1;
    #pragma unroll
    for (int i = 0; i < 32; i += 8) {
        int n = n0 + ty + i;
        int nd = (mode == 1) ? ((n < half) ? 2*n : 2*(n - half) + 1) : n;
        dst[(size_t)nd*Kd + k0+tx] = __float2half_rn(ts[tx][ty+i]);
    }
}

// ---------------- RMSNorm + FiLM (float4 in, half out) ----------------
__global__ void rmsnorm_film_kernel(const float* __restrict__ x, const float* __restrict__ w,
                                    const float* __restrict__ gamma, const float* __restrict__ beta,
                                    __half* __restrict__ y)
{
    int row = blockIdx.x;
    int b = row / TT;
    const float* xr = x + (size_t)row * DD;
    __half* yr = y + (size_t)row * DD;
    int d4 = threadIdx.x * 4;
    float4 v = *reinterpret_cast<const float4*>(&xr[d4]);
    float s = v.x*v.x + v.y*v.y + v.z*v.z + v.w*v.w;
    __shared__ float red[256];
    red[threadIdx.x] = s; __syncthreads();
    for (int o = 128; o > 0; o >>= 1) {
        if (threadIdx.x < o) red[threadIdx.x] += red[threadIdx.x + o];
        __syncthreads();
    }
    float rs = rsqrtf(red[0] * (1.0f/DD) + 1e-6f);
    float4 wv = *reinterpret_cast<const float4*>(&w[d4]);
    float4 gv = *reinterpret_cast<const float4*>(&gamma[b*DD + d4]);
    float4 bv = *reinterpret_cast<const float4*>(&beta[b*DD + d4]);
    __half2 h0 = __floats2half2_rn(wv.x * v.x * rs * (gv.x + 1.0f) + bv.x,
                                   wv.y * v.y * rs * (gv.y + 1.0f) + bv.y);
    __half2 h1 = __floats2half2_rn(wv.z * v.z * rs * (gv.z + 1.0f) + bv.z,
                                   wv.w * v.w * rs * (gv.w + 1.0f) + bv.w);
    *reinterpret_cast<__half2*>(&yr[d4])   = h0;
    *reinterpret_cast<__half2*>(&yr[d4+2]) = h1;
}

// ---------------- FP16 tensor-core GEMM 64x128 tile, 128 threads (4 CTA/SM) ----------------
// OUT_MODE 0: C fp32 (+Res) ; 1: Ch half ; 2: Ch half geglu (N/2 cols, permuted w)
#define GBM 64
#define GBN 128
#define GBK 32
#define HPAD 8

template<int OUT_MODE>
__global__ __launch_bounds__(128) void gemm_f16_kernel(int M, int N, int K,
    const __half* __restrict__ A, const __half* __restrict__ Bt,
    const float* __restrict__ Res, float* __restrict__ C, __half* __restrict__ Ch)
{
    __shared__ __half As[2][GBM][GBK+HPAD];
    __shared__ __half Bs[2][GBN][GBK+HPAD];

    int tid = threadIdx.x;
    int wid = tid >> 5, lane = tid & 31;
    int wn = wid;                          // 4 warps over 128 n; warp tile 64x32

    const __half* Ag = A  + (size_t)blockIdx.y * GBM * K;
    const __half* Bg = Bt + (size_t)blockIdx.x * GBN * K;

    float acc[4][4][4];
    #pragma unroll
    for (int i = 0; i < 4; i++)
        #pragma unroll
        for (int j = 0; j < 4; j++)
            #pragma unroll
            for (int r = 0; r < 4; r++) acc[i][j][r] = 0.f;

    int lr = tid >> 2, lc = (tid & 3) * 8;   // 32 rows per round

    #define LOAD_STAGE(buf, kt) do { \
        asm volatile("cp.async.cg.shared.global [%0], [%1], 16;\n" \
            :: "r"(smem_u32(&As[buf][lr][lc])),    "l"(Ag + (size_t)lr*K + (kt) + lc)); \
        asm volatile("cp.async.cg.shared.global [%0], [%1], 16;\n" \
            :: "r"(smem_u32(&As[buf][lr+32][lc])), "l"(Ag + (size_t)(lr+32)*K + (kt) + lc)); \
        asm volatile("cp.async.cg.shared.global [%0], [%1], 16;\n" \
            :: "r"(smem_u32(&Bs[buf][lr][lc])),    "l"(Bg + (size_t)lr*K + (kt) + lc)); \
        asm volatile("cp.async.cg.shared.global [%0], [%1], 16;\n" \
            :: "r"(smem_u32(&Bs[buf][lr+32][lc])), "l"(Bg + (size_t)(lr+32)*K + (kt) + lc)); \
        asm volatile("cp.async.cg.shared.global [%0], [%1], 16;\n" \
            :: "r"(smem_u32(&Bs[buf][lr+64][lc])), "l"(Bg + (size_t)(lr+64)*K + (kt) + lc)); \
        asm volatile("cp.async.cg.shared.global [%0], [%1], 16;\n" \
            :: "r"(smem_u32(&Bs[buf][lr+96][lc])), "l"(Bg + (size_t)(lr+96)*K + (kt) + lc)); \
        asm volatile("cp.async.commit_group;\n"); \
    } while (0)

    int nk = K / GBK;
    LOAD_STAGE(0, 0);

    for (int t = 0; t < nk; t++) {
        if (t + 1 < nk) LOAD_STAGE((t+1) & 1, (t+1) * GBK);
        else            asm volatile("cp.async.commit_group;\n");
        asm volatile("cp.async.wait_group 1;\n");
        __syncthreads();

        int buf = t & 1;
        #pragma unroll
        for (int kk = 0; kk < 2; kk++) {
            int k0 = kk * 16;
            int kc = k0 + (lane >> 4) * 8;
            unsigned af[4][4];
            unsigned bf[2][4];
            #pragma unroll
            for (int i = 0; i < 4; i++) {
                int m = i*16 + (lane & 15);
                asm volatile("ldmatrix.sync.aligned.m8n8.x4.shared.b16 {%0,%1,%2,%3}, [%4];\n"
                    : "=r"(af[i][0]), "=r"(af[i][1]), "=r"(af[i][2]), "=r"(af[i][3])
                    : "r"(smem_u32(&As[buf][m][kc])));
            }
            #pragma unroll
            for (int jb = 0; jb < 2; jb++) {
                int n = wn*32 + jb*16 + (lane & 15);
                asm volatile("ldmatrix.sync.aligned.m8n8.x4.shared.b16 {%0,%1,%2,%3}, [%4];\n"
                    : "=r"(bf[jb][0]), "=r"(bf[jb][1]), "=r"(bf[jb][2]), "=r"(bf[jb][3])
                    : "r"(smem_u32(&Bs[buf][n][kc])));
            }
            #pragma unroll
            for (int i = 0; i < 4; i++)
                #pragma unroll
                for (int j = 0; j < 4; j++) {
                    int jb = j >> 1, p = j & 1;
                    asm volatile(
                        "mma.sync.aligned.m16n8k16.row.col.f32.f16.f16.f32 "
                        "{%0,%1,%2,%3}, {%4,%5,%6,%7}, {%8,%9}, {%0,%1,%2,%3};\n"
                        : "+f"(acc[i][j][0]), "+f"(acc[i][j][1]), "+f"(acc[i][j][2]), "+f"(acc[i][j][3])
                        : "r"(af[i][0]), "r"(af[i][1]), "r"(af[i][2]), "r"(af[i][3]),
                          "r"(bf[jb][p]), "r"(bf[jb][p+2]));
                }
        }
        __syncthreads();
    }
    #undef LOAD_STAGE

    if (OUT_MODE == 2) {
        int Ng = N >> 1;
        __half* Cg = Ch + (size_t)blockIdx.y * GBM * Ng + blockIdx.x * (GBN >> 1);
        #pragma unroll
        for (int i = 0; i < 4; i++) {
            int r0 = i*16 + (lane >> 2);
            int r1 = r0 + 8;
            #pragma unroll
            for (int j = 0; j < 4; j++) {
                int gc = (wn*32 + j*8 + (lane & 3) * 2) >> 1;
                float p1a = acc[i][j][0], p2a = acc[i][j][1];
                float p1b = acc[i][j][2], p2b = acc[i][j][3];
                float ga = 0.5f * p2a * (1.0f + erff(p2a * 0.70710678118654752f));
                float gb = 0.5f * p2b * (1.0f + erff(p2b * 0.70710678118654752f));
                Cg[(size_t)r0*Ng + gc] = __float2half_rn(p1a * ga);
                Cg[(size_t)r1*Ng + gc] = __float2half_rn(p1b * gb);
            }
        }
    } else if (OUT_MODE == 1) {
        __half* Cg = Ch + (size_t)blockIdx.y * GBM * N + blockIdx.x * GBN;
        #pragma unroll
        for (int i = 0; i < 4; i++) {
            int r0 = i*16 + (lane >> 2);
            int r1 = r0 + 8;
            #pragma unroll
            for (int j = 0; j < 4; j++) {
                int c0 = wn*32 + j*8 + (lane & 3) * 2;
                *reinterpret_cast<__half2*>(&Cg[(size_t)r0*N + c0]) =
                    __floats2half2_rn(acc[i][j][0], acc[i][j][1]);
                *reinterpret_cast<__half2*>(&Cg[(size_t)r1*N + c0]) =
                    __floats2half2_rn(acc[i][j][2], acc[i][j][3]);
            }
        }
    } else {
        float* Cg = C + (size_t)blockIdx.y * GBM * N + blockIdx.x * GBN;
        const float* Rg = Res ? Res + (size_t)blockIdx.y * GBM * N + blockIdx.x * GBN : nullptr;
        #pragma unroll
        for (int i = 0; i < 4; i++) {
            int r0 = i*16 + (lane >> 2);
            int r1 = r0 + 8;
            #pragma unroll
            for (int j = 0; j < 4; j++) {
                int c0 = wn*32 + j*8 + (lane & 3) * 2;
                float v0 = acc[i][j][0], v1 = acc[i][j][1];
                float v2 = acc[i][j][2], v3 = acc[i][j][3];
                if (Rg) {
                    v0 += Rg[(size_t)r0*N + c0];   v1 += Rg[(size_t)r0*N + c0+1];
                    v2 += Rg[(size_t)r1*N + c0];   v3 += Rg[(size_t)r1*N + c0+1];
                }
                Cg[(size_t)r0*N + c0]   = v0;  Cg[(size_t)r0*N + c0+1] = v1;
                Cg[(size_t)r1*N + c0]   = v2;  Cg[(size_t)r1*N + c0+1] = v3;
            }
        }
    }
}

// ---------------- fused flash attention (fp16 mma k16, packed qkv, bitmask) ----------------
#define FPITCH 72
#define QKVD (3*DD)

struct FlashSmemH {
    __half Qh[64][FPITCH];
    __half Kh[64][FPITCH];
    __half Vh[64][FPITCH];
    __half Ph[4][16][FPITCH];
    float  Sb[128];
};

__global__ __launch_bounds__(128) void flash_attn_kernel()
{
    __shared__ FlashSmemH S;

    int qt = blockIdx.x, bh = blockIdx.y;
    int b = bh / HH, h = bh % HH;
    int q0 = qt * 64;
    int tid = threadIdx.x, wid = tid >> 5, lane = tid & 31;
    int lq = lane >> 2, lk = lane & 3;
    int qrel = wid*16 + lq;

    const __half2 qscale = __floats2half2_rn(0.125f, 0.125f);
    for (int i = tid; i < 64*16; i += 128) {
        int r = i >> 4, c4 = (i & 15) * 4;
        size_t off = (size_t)(b*TT + q0 + r)*QKVD + h*DHH + c4;
        __half2 a0 = *reinterpret_cast<const __half2*>(&g_qkv_h[off]);
        __half2 a1 = *reinterpret_cast<const __half2*>(&g_qkv_h[off+2]);
        *reinterpret_cast<__half2*>(&S.Qh[r][c4])   = __hmul2(a0, qscale);
        *reinterpret_cast<__half2*>(&S.Qh[r][c4+2]) = __hmul2(a1, qscale);
    }

    float o[8][4];
    #pragma unroll
    for (int n = 0; n < 8; n++)
        #pragma unroll
        for (int r = 0; r < 4; r++) o[n][r] = 0.f;
    float mrow[2] = { -3.0e38f, -3.0e38f };
    float lrow[2] = { 0.f, 0.f };

    for (int kt0 = 0; kt0 < TT; kt0 += 64) {
        __syncthreads();
        for (int i = tid; i < 64*16; i += 128) {
            int r = i >> 4, c4 = (i & 15) * 4;
            size_t off = (size_t)(b*TT + kt0 + r)*QKVD + h*DHH + c4;
            *reinterpret_cast<uint2*>(&S.Kh[r][c4]) =
                *reinterpret_cast<const uint2*>(&g_qkv_h[off + DD]);
            *reinterpret_cast<uint2*>(&S.Vh[r][c4]) =
                *reinterpret_cast<const uint2*>(&g_qkv_h[off + 2*DD]);
        }
        if (tid < 127) S.Sb[tid] = g_biasrel[h*2048 + (kt0 - q0 + 960) + tid];
        __syncthreads();

        // ---- S = Q @ K^T ----
        float sacc[8][4];
        #pragma unroll
        for (int n = 0; n < 8; n++)
            #pragma unroll
            for (int r = 0; r < 4; r++) sacc[n][r] = 0.f;

        #pragma unroll
        for (int ks = 0; ks < 4; ks++) {
            int kc = ks*16 + (lane >> 4) * 8;
            unsigned aq[4];
            asm volatile("ldmatrix.sync.aligned.m8n8.x4.shared.b16 {%0,%1,%2,%3}, [%4];\n"
                : "=r"(aq[0]), "=r"(aq[1]), "=r"(aq[2]), "=r"(aq[3])
                : "r"(smem_u32(&S.Qh[wid*16 + (lane & 15)][kc])));
            unsigned bk[4][4];
            #pragma unroll
            for (int jb = 0; jb < 4; jb++) {
                asm volatile("ldmatrix.sync.aligned.m8n8.x4.shared.b16 {%0,%1,%2,%3}, [%4];\n"
                    : "=r"(bk[jb][0]), "=r"(bk[jb][1]), "=r"(bk[jb][2]), "=r"(bk[jb][3])
                    : "r"(smem_u32(&S.Kh[jb*16 + (lane & 15)][kc])));
            }
            #pragma unroll
            for (int n8 = 0; n8 < 8; n8++) {
                int jb = n8 >> 1, p = n8 & 1;
                asm volatile(
                    "mma.sync.aligned.m16n8k16.row.col.f32.f16.f16.f32 "
                    "{%0,%1,%2,%3}, {%4,%5,%6,%7}, {%8,%9}, {%0,%1,%2,%3};\n"
                    : "+f"(sacc[n8][0]), "+f"(sacc[n8][1]), "+f"(sacc[n8][2]), "+f"(sacc[n8][3])
                    : "r"(aq[0]), "r"(aq[1]), "r"(aq[2]), "r"(aq[3]),
                      "r"(bk[jb][p]), "r"(bk[jb][p+2]));
            }
        }

        // ---- bias + bitmask + online softmax ----
        unsigned long long mm[2];
        #pragma unroll
        for (int e = 0; e < 2; e++) {
            int row = b*TT + q0 + qrel + e*8;
            unsigned w0 = g_maskbits[row*32 + (kt0 >> 5)];
            unsigned w1 = g_maskbits[row*32 + (kt0 >> 5) + 1];
            mm[e] = ((unsigned long long)w1 << 32) | w0;
        }
        float mnew[2] = { mrow[0], mrow[1] };
        #pragma unroll
        for (int n = 0; n < 8; n++) {
            #pragma unroll
            for (int e = 0; e < 2; e++) {
                int qr = qrel + e*8;
                #pragma unroll
                for (int c = 0; c < 2; c++) {
                    int kr = n*8 + 2*lk + c;
                    float s = sacc[n][e*2+c] + S.Sb[kr - qr + 63];
                    if (!((mm[e] >> kr) & 1ull)) s = -1e9f;
                    sacc[n][e*2+c] = s;
                    mnew[e] = fmaxf(mnew[e], s);
                }
            }
        }
        #pragma unroll
        for (int e = 0; e < 2; e++) {
            mnew[e] = fmaxf(mnew[e], __shfl_xor_sync(0xffffffffu, mnew[e], 1));
            mnew[e] = fmaxf(mnew[e], __shfl_xor_sync(0xffffffffu, mnew[e], 2));
        }
        float alpha[2], rs[2] = {0.f, 0.f};
        alpha[0] = __expf(mrow[0] - mnew[0]);
        alpha[1] = __expf(mrow[1] - mnew[1]);
        mrow[0] = mnew[0]; mrow[1] = mnew[1];

        #pragma unroll
        for (int n = 0; n < 8; n++) {
            #pragma unroll
            for (int e = 0; e < 2; e++) {
                float p0 = __expf(sacc[n][e*2+0] - mnew[e]);
                float p1 = __expf(sacc[n][e*2+1] - mnew[e]);
                rs[e] += p0 + p1;
                *reinterpret_cast<__half2*>(&S.Ph[wid][lq + e*8][n*8 + 2*lk]) =
                    __floats2half2_rn(p0, p1);
            }
        }
        #pragma unroll
        for (int e = 0; e < 2; e++) {
            rs[e] += __shfl_xor_sync(0xffffffffu, rs[e], 1);
            rs[e] += __shfl_xor_sync(0xffffffffu, rs[e], 2);
            lrow[e] = lrow[e] * alpha[e] + rs[e];
        }
        #pragma unroll
        for (int n = 0; n < 8; n++) {
            o[n][0] *= alpha[0]; o[n][1] *= alpha[0];
            o[n][2] *= alpha[1]; o[n][3] *= alpha[1];
        }
        __syncwarp();

        // ---- O += P @ V ----
        #pragma unroll
        for (int ks = 0; ks < 4; ks++) {
            int kc = ks*16 + (lane >> 4) * 8;
            unsigned ap[4];
            asm volatile("ldmatrix.sync.aligned.m8n8.x4.shared.b16 {%0,%1,%2,%3}, [%4];\n"
                : "=r"(ap[0]), "=r"(ap[1]), "=r"(ap[2]), "=r"(ap[3])
                : "r"(smem_u32(&S.Ph[wid][lane & 15][kc])));
            int vrow = ks*16 + (lane & 7) + ((lane >> 3) & 1) * 8;
            unsigned bv[4][4];
            #pragma unroll
            for (int jb = 0; jb < 4; jb++) {
                int vcol = jb*16 + ((lane >> 4) & 1) * 8;
                asm volatile("ldmatrix.sync.aligned.m8n8.x4.trans.shared.b16 {%0,%1,%2,%3}, [%4];\n"
                    : "=r"(bv[jb][0]), "=r"(bv[jb][1]), "=r"(bv[jb][2]), "=r"(bv[jb][3])
                    : "r"(smem_u32(&S.Vh[vrow][vcol])));
            }
            #pragma unroll
            for (int n8 = 0; n8 < 8; n8++) {
                int jb = n8 >> 1, q2 = n8 & 1;
                asm volatile(
                    "mma.sync.aligned.m16n8k16.row.col.f32.f16.f16.f32 "
                    "{%0,%1,%2,%3}, {%4,%5,%6,%7}, {%8,%9}, {%0,%1,%2,%3};\n"
                    : "+f"(o[n8][0]), "+f"(o[n8][1]), "+f"(o[n8][2]), "+f"(o[n8][3])
                    : "r"(ap[0]), "r"(ap[1]), "r"(ap[2]), "r"(ap[3]),
                      "r"(bv[jb][2*q2]), "r"(bv[jb][2*q2+1]));
            }
        }
        __syncwarp();
    }

    float inv0 = 1.0f / lrow[0], inv1 = 1.0f / lrow[1];
    #pragma unroll
    for (int e = 0; e < 2; e++) {
        int qg = b*TT + q0 + qrel + e*8;
        float inv = e ? inv1 : inv0;
        #pragma unroll
        for (int n = 0; n < 8; n++) {
            __half2 hw = __floats2half2_rn(o[n][e*2+0] * inv, o[n][e*2+1] * inv);
            *reinterpret_cast<__half2*>(&g_ctx_h[(size_t)qg*DD + h*DHH + n*8 + 2*lk]) = hw;
        }
    }
}

// ---------------- host launcher ----------------
extern "C" void kernel_launch(void* const* d_in, const int* in_sizes, int n_in,
                              void* d_out, int out_size)
{
    const float* x       = (const float*)d_in[0];
    const int*   mask    = (const int*)  d_in[1];
    const float* cond    = (const float*)d_in[2];
    const float* norm1_w = (const float*)d_in[3];
    const float* f1gw    = (const float*)d_in[4];
    const float* f1gb    = (const float*)d_in[5];
    const float* f1bw    = (const float*)d_in[6];
    const float* f1bb    = (const float*)d_in[7];
    const float* wq      = (const float*)d_in[8];
    const float* wk      = (const float*)d_in[9];
    const float* wv      = (const float*)d_in[10];
    const float* wo      = (const float*)d_in[11];
    const float* rel_emb = (const float*)d_in[12];
    const float* norm3_w = (const float*)d_in[13];
    const float* f3gw    = (const float*)d_in[14];
    const float* f3gb    = (const float*)d_in[15];
    const float* f3bw    = (const float*)d_in[16];
    const float* f3bb    = (const float*)d_in[17];
    const float* w1      = (const float*)d_in[18];
    const float* w2      = (const float*)d_in[19];
    float* out = (float*)d_out;
    float* outbias = (out_size >= BTD + BIAS_ELEMS) ? out + BTD : nullptr;

    float *p_x1;
    float *p_g1, *p_b1, *p_g3, *p_b3;
    __half *p_y_h, *p_qkv_h, *p_ctx_h, *p_gg_h;
    __half *p_wqkvT, *p_woT, *p_w1T, *p_w2T;
    cudaGetSymbolAddress((void**)&p_g1, g_gamma1);
    cudaGetSymbolAddress((void**)&p_b1, g_beta1);
    cudaGetSymbolAddress((void**)&p_g3, g_gamma3);
    cudaGetSymbolAddress((void**)&p_b3, g_beta3);
    cudaGetSymbolAddress((void**)&p_x1, g_x1);
    cudaGetSymbolAddress((void**)&p_y_h,  g_y_h);
    cudaGetSymbolAddress((void**)&p_qkv_h, g_qkv_h);
    cudaGetSymbolAddress((void**)&p_ctx_h, g_ctx_h);
    cudaGetSymbolAddress((void**)&p_gg_h, g_gg_h);
    cudaGetSymbolAddress((void**)&p_wqkvT, g_wqkvT);
    cudaGetSymbolAddress((void**)&p_woT, g_woT);
    cudaGetSymbolAddress((void**)&p_w1T, g_w1T);
    cudaGetSymbolAddress((void**)&p_w2T, g_w2T);

    // 0) transposes + mask bits + FiLM + bias (independent prologue work)
    dim3 tb(32, 8);
    transpose_h_kernel<<<dim3(DD/32, DD/32), tb>>>(wq, p_wqkvT,           DD, DD, 0);
    transpose_h_kernel<<<dim3(DD/32, DD/32), tb>>>(wk, p_wqkvT + DD*DD,   DD, DD, 0);
    transpose_h_kernel<<<dim3(DD/32, DD/32), tb>>>(wv, p_wqkvT + 2*DD*DD, DD, DD, 0);
    transpose_h_kernel<<<dim3(DD/32, DD/32), tb>>>(wo, p_woT, DD, DD, 0);
    transpose_h_kernel<<<dim3(4*DD/32, DD/32), tb>>>(w1, p_w1T, DD, 4*DD, 1);
    transpose_h_kernel<<<dim3(DD/32, 2*DD/32), tb>>>(w2, p_w2T, 2*DD, DD, 0);
    maskbits_kernel<<<BT/8, 256>>>(mask);

    film_params_kernel<<<(BB*DD + 255)/256, 256>>>(cond, f1gw, f1gb, f1bw, f1bb,
                                                   f3gw, f3gb, f3bw, f3bb);
    biasrel_kernel<<<(2047 + 255)/256, 256>>>(rel_emb);
    if (outbias)
        bias_out_kernel<<<(TT*TT + 255)/256, 256>>>(rel_emb, outbias);

    // 2) y = film(rmsnorm(x)) -> half
    rmsnorm_film_kernel<<<BT, 256>>>(x, norm1_w, p_g1, p_b1, p_y_h);

    // 3) merged QKV projection (half packed output)
    gemm_f16_kernel<1><<<dim3(3*DD/GBN, BT/GBM), 128>>>(BT, 3*DD, DD, p_y_h, p_wqkvT,
                                                        nullptr, nullptr, p_qkv_h);

    // 4) fused flash attention (fp16, bitmask) -> half ctx
    flash_attn_kernel<<<dim3(TT/64, BB*HH), 128>>>();

    // 5) output projection + residual -> x1 (fp32)
    gemm_f16_kernel<0><<<dim3(DD/GBN, BT/GBM), 128>>>(BT, DD, DD, p_ctx_h, p_woT,
                                                      x, p_x1, nullptr);

    // 6) y2 = film3(rmsnorm(x1)) -> half
    rmsnorm_film_kernel<<<BT, 256>>>(p_x1, norm3_w, p_g3, p_b3, p_y_h);

    // 7) FFN: fused ffn1+geglu -> half gg ; ffn2 + residual -> out
    gemm_f16_kernel<2><<<dim3(4*DD/GBN, BT/GBM), 128>>>(BT, 4*DD, DD, p_y_h, p_w1T,
                                                        nullptr, nullptr, p_gg_h);
    gemm_f16_kernel<0><<<dim3(DD/GBN, BT/GBM), 128>>>(BT, DD, 2*DD, p_gg_h, p_w2T,
                                                      p_x1, out, nullptr);
}

// round 16
// speedup vs baseline: 1.2129x; 1.0199x over previous
#include <cuda_runtime.h>
#include <cuda_fp16.h>
#include <math.h>

#define BB 4
#define TT 1024
#define DD 1024
#define HH 16
#define DHH 64
#define DCC 64
#define BT (BB*TT)        // 4096
#define BTD (BB*TT*DD)    // 4194304
#define BIAS_ELEMS (HH*TT*TT) // 16777216

// ---------------- scratch (device globals; no allocation) ----------------
__device__ float g_gamma1[BB*DD];
__device__ float g_beta1 [BB*DD];
__device__ float g_gamma3[BB*DD];
__device__ float g_beta3 [BB*DD];
__device__ float g_x1  [BTD];
__device__ float g_biasrel[HH*2048];
__device__ unsigned g_maskbits[BT*32];
// fp16 activation/weight buffers
__device__ __half g_y_h  [BTD];
__device__ __half g_qkv_h[(size_t)BT*3*DD];
__device__ __half g_ctx_h[BTD];
__device__ __half g_gg_h [(size_t)BT*2*DD];
__device__ __half g_wqkvT[(size_t)3*DD*DD];
__device__ __half g_woT[DD*DD];
__device__ __half g_w1T[(size_t)4*DD*DD];     // geglu-permuted rows
__device__ __half g_w2T[(size_t)2*DD*DD];

__device__ __forceinline__ unsigned smem_u32(const void* p) {
    return (unsigned)__cvta_generic_to_shared(p);
}

// ---------------- FiLM params ----------------
__global__ void film_params_kernel(const float* __restrict__ cond,
    const float* __restrict__ g1w, const float* __restrict__ g1b,
    const float* __restrict__ b1w, const float* __restrict__ b1b,
    const float* __restrict__ g3w, const float* __restrict__ g3b,
    const float* __restrict__ b3w, const float* __restrict__ b3b)
{
    int idx = blockIdx.x * blockDim.x + threadIdx.x;
    if (idx >= BB*DD) return;
    int b = idx / DD, d = idx % DD;
    float s1 = 0.f, s2 = 0.f, s3 = 0.f, s4 = 0.f;
    #pragma unroll 8
    for (int c = 0; c < DCC; c++) {
        float cv = cond[b*DCC + c];
        s1 += cv * g1w[c*DD + d];
        s2 += cv * b1w[c*DD + d];
        s3 += cv * g3w[c*DD + d];
        s4 += cv * b3w[c*DD + d];
    }
    g_gamma1[idx] = s1 + g1b[d];
    g_beta1 [idx] = s2 + b1b[d];
    g_gamma3[idx] = s3 + g3b[d];
    g_beta3 [idx] = s4 + b3b[d];
}

// ---------------- T5 bucket ----------------
__device__ __forceinline__ int t5_bucket(int rp) {
    int bucket = (rp > 0) ? 16 : 0;
    int arp = rp < 0 ? -rp : rp;
    int off;
    if (arp < 8) {
        off = arp;
    } else {
        float l = logf((float)arp * 0.125f) / logf(16.0f) * 8.0f;
        off = 8 + (int)l;
        if (off > 15) off = 15;
    }
    return bucket + off;
}

__global__ void biasrel_kernel(const float* __restrict__ rel_emb)
{
    int idx = blockIdx.x * blockDim.x + threadIdx.x;
    if (idx >= 2047) return;
    int bucket = t5_bucket(idx - 1023);
    #pragma unroll
    for (int h = 0; h < HH; h++)
        g_biasrel[h*2048 + idx] = rel_emb[bucket*HH + h];
}

__global__ void bias_out_kernel(const float* __restrict__ rel_emb, float* __restrict__ outbias)
{
    int idx = blockIdx.x * blockDim.x + threadIdx.x;
    if (idx >= TT*TT) return;
    int q = idx / TT, k = idx % TT;
    int bucket = t5_bucket(k - q);
    #pragma unroll
    for (int h = 0; h < HH; h++)
        outbias[(size_t)h*TT*TT + idx] = rel_emb[bucket*HH + h];
}

// ---------------- mask -> bitmask ----------------
__global__ void maskbits_kernel(const int* __restrict__ mask)
{
    int warp = (blockIdx.x * blockDim.x + threadIdx.x) >> 5;
    int lane = threadIdx.x & 31;
    if (warp >= BT) return;
    const int* mrow = mask + (size_t)warp * TT;
    #pragma unroll 4
    for (int w = 0; w < 32; w++) {
        unsigned word = __ballot_sync(0xffffffffu, mrow[w*32 + lane] != 0);
        if (lane == 0) g_maskbits[warp*32 + w] = word;
    }
}

// ---------------- weight transpose -> half K-major ----------------
__global__ void transpose_h_kernel(const float* __restrict__ src, __half* __restrict__ dst,
                                   int Kd, int Nd, int mode)
{
    __shared__ float ts[32][33];
    int n0 = blockIdx.x*32, k0 = blockIdx.y*32;
    int tx = threadIdx.x, ty = threadIdx.y;   // 32 x 8
    #pragma unroll
    for (int i = 0; i < 32; i += 8)
        ts[ty+i][tx] = src[(size_t)(k0+ty+i)*Nd + n0+tx];
    __syncthreads();
    int half = Nd >> 1;
    #pragma unroll
    for (int i = 0; i < 32; i += 8) {
        int n = n0 + ty + i;
        int nd = (mode == 1) ? ((n < half) ? 2*n : 2*(n - half) + 1) : n;
        dst[(size_t)nd*Kd + k0+tx] = __float2half_rn(ts[tx][ty+i]);
    }
}

// ---------------- RMSNorm + FiLM ----------------
__global__ void rmsnorm_film_kernel(const float* __restrict__ x, const float* __restrict__ w,
                                    const float* __restrict__ gamma, const float* __restrict__ beta,
                                    __half* __restrict__ y)
{
    int row = blockIdx.x;
    int b = row / TT;
    const float* xr = x + (size_t)row * DD;
    __half* yr = y + (size_t)row * DD;
    int d4 = threadIdx.x * 4;
    float4 v = *reinterpret_cast<const float4*>(&xr[d4]);
    float s = v.x*v.x + v.y*v.y + v.z*v.z + v.w*v.w;
    __shared__ float red[256];
    red[threadIdx.x] = s; __syncthreads();
    for (int o = 128; o > 0; o >>= 1) {
        if (threadIdx.x < o) red[threadIdx.x] += red[threadIdx.x + o];
        __syncthreads();
    }
    float rs = rsqrtf(red[0] * (1.0f/DD) + 1e-6f);
    float4 wv = *reinterpret_cast<const float4*>(&w[d4]);
    float4 gv = *reinterpret_cast<const float4*>(&gamma[b*DD + d4]);
    float4 bv = *reinterpret_cast<const float4*>(&beta[b*DD + d4]);
    __half2 h0 = __floats2half2_rn(wv.x * v.x * rs * (gv.x + 1.0f) + bv.x,
                                   wv.y * v.y * rs * (gv.y + 1.0f) + bv.y);
    __half2 h1 = __floats2half2_rn(wv.z * v.z * rs * (gv.z + 1.0f) + bv.z,
                                   wv.w * v.w * rs * (gv.w + 1.0f) + bv.w);
    *reinterpret_cast<__half2*>(&yr[d4])   = h0;
    *reinterpret_cast<__half2*>(&yr[d4+2]) = h1;
}

// ---------------- FP16 GEMM 64x128 tile, 128 threads, 3-stage cp.async ----------------
// OUT_MODE 0: C fp32 (+Res) ; 1: Ch half ; 2: Ch half geglu
#define GBM 64
#define GBN 128
#define GBK 32
#define HPAD 8

template<int OUT_MODE>
__global__ __launch_bounds__(128) void gemm_f16_kernel(int M, int N, int K,
    const __half* __restrict__ A, const __half* __restrict__ Bt,
    const float* __restrict__ Res, float* __restrict__ C, __half* __restrict__ Ch)
{
    __shared__ __half As[3][GBM][GBK+HPAD];
    __shared__ __half Bs[3][GBN][GBK+HPAD];

    int tid = threadIdx.x;
    int wid = tid >> 5, lane = tid & 31;
    int wn = wid;

    const __half* Ag = A  + (size_t)blockIdx.y * GBM * K;
    const __half* Bg = Bt + (size_t)blockIdx.x * GBN * K;

    float acc[4][4][4];
    #pragma unroll
    for (int i = 0; i < 4; i++)
        #pragma unroll
        for (int j = 0; j < 4; j++)
            #pragma unroll
            for (int r = 0; r < 4; r++) acc[i][j][r] = 0.f;

    int lr = tid >> 2, lc = (tid & 3) * 8;

    #define LOAD_STAGE(buf, kt) do { \
        asm volatile("cp.async.cg.shared.global [%0], [%1], 16;\n" \
            :: "r"(smem_u32(&As[buf][lr][lc])),    "l"(Ag + (size_t)lr*K + (kt) + lc)); \
        asm volatile("cp.async.cg.shared.global [%0], [%1], 16;\n" \
            :: "r"(smem_u32(&As[buf][lr+32][lc])), "l"(Ag + (size_t)(lr+32)*K + (kt) + lc)); \
        asm volatile("cp.async.cg.shared.global [%0], [%1], 16;\n" \
            :: "r"(smem_u32(&Bs[buf][lr][lc])),    "l"(Bg + (size_t)lr*K + (kt) + lc)); \
        asm volatile("cp.async.cg.shared.global [%0], [%1], 16;\n" \
            :: "r"(smem_u32(&Bs[buf][lr+32][lc])), "l"(Bg + (size_t)(lr+32)*K + (kt) + lc)); \
        asm volatile("cp.async.cg.shared.global [%0], [%1], 16;\n" \
            :: "r"(smem_u32(&Bs[buf][lr+64][lc])), "l"(Bg + (size_t)(lr+64)*K + (kt) + lc)); \
        asm volatile("cp.async.cg.shared.global [%0], [%1], 16;\n" \
            :: "r"(smem_u32(&Bs[buf][lr+96][lc])), "l"(Bg + (size_t)(lr+96)*K + (kt) + lc)); \
        asm volatile("cp.async.commit_group;\n"); \
    } while (0)

    int nk = K / GBK;
    LOAD_STAGE(0, 0);
    LOAD_STAGE(1, GBK);

    int bufc = 0;     // stage holding tile t
    for (int t = 0; t < nk; t++) {
        int bufn = bufc + 2; if (bufn >= 3) bufn -= 3;
        if (t + 2 < nk) LOAD_STAGE(bufn, (t+2) * GBK);
        else            asm volatile("cp.async.commit_group;\n");
        asm volatile("cp.async.wait_group 2;\n");
        __syncthreads();

        #pragma unroll
        for (int kk = 0; kk < 2; kk++) {
            int k0 = kk * 16;
            int kc = k0 + (lane >> 4) * 8;
            unsigned af[4][4];
            unsigned bf[2][4];
            #pragma unroll
            for (int i = 0; i < 4; i++) {
                int m = i*16 + (lane & 15);
                asm volatile("ldmatrix.sync.aligned.m8n8.x4.shared.b16 {%0,%1,%2,%3}, [%4];\n"
                    : "=r"(af[i][0]), "=r"(af[i][1]), "=r"(af[i][2]), "=r"(af[i][3])
                    : "r"(smem_u32(&As[bufc][m][kc])));
            }
            #pragma unroll
            for (int jb = 0; jb < 2; jb++) {
                int n = wn*32 + jb*16 + (lane & 15);
                asm volatile("ldmatrix.sync.aligned.m8n8.x4.shared.b16 {%0,%1,%2,%3}, [%4];\n"
                    : "=r"(bf[jb][0]), "=r"(bf[jb][1]), "=r"(bf[jb][2]), "=r"(bf[jb][3])
                    : "r"(smem_u32(&Bs[bufc][n][kc])));
            }
            #pragma unroll
            for (int i = 0; i < 4; i++)
                #pragma unroll
                for (int j = 0; j < 4; j++) {
                    int jb = j >> 1, p = j & 1;
                    asm volatile(
                        "mma.sync.aligned.m16n8k16.row.col.f32.f16.f16.f32 "
                        "{%0,%1,%2,%3}, {%4,%5,%6,%7}, {%8,%9}, {%0,%1,%2,%3};\n"
                        : "+f"(acc[i][j][0]), "+f"(acc[i][j][1]), "+f"(acc[i][j][2]), "+f"(acc[i][j][3])
                        : "r"(af[i][0]), "r"(af[i][1]), "r"(af[i][2]), "r"(af[i][3]),
                          "r"(bf[jb][p]), "r"(bf[jb][p+2]));
                }
        }
        __syncthreads();
        bufc = bufc + 1; if (bufc >= 3) bufc -= 3;
    }
    #undef LOAD_STAGE

    if (OUT_MODE == 2) {
        int Ng = N >> 1;
        __half* Cg = Ch + (size_t)blockIdx.y * GBM * Ng + blockIdx.x * (GBN >> 1);
        #pragma unroll
        for (int i = 0; i < 4; i++) {
            int r0 = i*16 + (lane >> 2);
            int r1 = r0 + 8;
            #pragma unroll
            for (int j = 0; j < 4; j++) {
                int gc = (wn*32 + j*8 + (lane & 3) * 2) >> 1;
                float p1a = acc[i][j][0], p2a = acc[i][j][1];
                float p1b = acc[i][j][2], p2b = acc[i][j][3];
                float ga = 0.5f * p2a * (1.0f + erff(p2a * 0.70710678118654752f));
                float gb = 0.5f * p2b * (1.0f + erff(p2b * 0.70710678118654752f));
                Cg[(size_t)r0*Ng + gc] = __float2half_rn(p1a * ga);
                Cg[(size_t)r1*Ng + gc] = __float2half_rn(p1b * gb);
            }
        }
    } else if (OUT_MODE == 1) {
        __half* Cg = Ch + (size_t)blockIdx.y * GBM * N + blockIdx.x * GBN;
        #pragma unroll
        for (int i = 0; i < 4; i++) {
            int r0 = i*16 + (lane >> 2);
            int r1 = r0 + 8;
            #pragma unroll
            for (int j = 0; j < 4; j++) {
                int c0 = wn*32 + j*8 + (lane & 3) * 2;
                *reinterpret_cast<__half2*>(&Cg[(size_t)r0*N + c0]) =
                    __floats2half2_rn(acc[i][j][0], acc[i][j][1]);
                *reinterpret_cast<__half2*>(&Cg[(size_t)r1*N + c0]) =
                    __floats2half2_rn(acc[i][j][2], acc[i][j][3]);
            }
        }
    } else {
        float* Cg = C + (size_t)blockIdx.y * GBM * N + blockIdx.x * GBN;
        const float* Rg = Res ? Res + (size_t)blockIdx.y * GBM * N + blockIdx.x * GBN : nullptr;
        #pragma unroll
        for (int i = 0; i < 4; i++) {
            int r0 = i*16 + (lane >> 2);
            int r1 = r0 + 8;
            #pragma unroll
            for (int j = 0; j < 4; j++) {
                int c0 = wn*32 + j*8 + (lane & 3) * 2;
                float v0 = acc[i][j][0], v1 = acc[i][j][1];
                float v2 = acc[i][j][2], v3 = acc[i][j][3];
                if (Rg) {
                    v0 += Rg[(size_t)r0*N + c0];   v1 += Rg[(size_t)r0*N + c0+1];
                    v2 += Rg[(size_t)r1*N + c0];   v3 += Rg[(size_t)r1*N + c0+1];
                }
                Cg[(size_t)r0*N + c0]   = v0;  Cg[(size_t)r0*N + c0+1] = v1;
                Cg[(size_t)r1*N + c0]   = v2;  Cg[(size_t)r1*N + c0+1] = v3;
            }
        }
    }
}

// ---------------- fused flash attention (fp16 mma k16, double-buffered cp.async) ----------------
#define FPITCH 72
#define QKVD (3*DD)

struct FlashSmemH2 {
    __half Qh[64][FPITCH];
    __half Kh[2][64][FPITCH];
    __half Vh[2][64][FPITCH];
    __half Ph[4][16][FPITCH];
    float  Sb[2][128];
};

__global__ __launch_bounds__(128) void flash_attn_kernel()
{
    extern __shared__ char fa_raw[];
    FlashSmemH2& S = *reinterpret_cast<FlashSmemH2*>(fa_raw);

    int qt = blockIdx.x, bh = blockIdx.y;
    int b = bh / HH, h = bh % HH;
    int q0 = qt * 64;
    int tid = threadIdx.x, wid = tid >> 5, lane = tid & 31;
    int lq = lane >> 2, lk = lane & 3;
    int qrel = wid*16 + lq;

    // per-thread K/V chunk: 4 chunks of 16B each (64 rows x 8 chunks/row over 128 threads)
    // chunk c = tid + j*128 ; row = c>>3 ; colh = (c&7)*8
    #define FA_LOAD_TILE(buf, kt0) do { \
        _Pragma("unroll") \
        for (int j = 0; j < 4; j++) { \
            int c = tid + j*128; \
            int r = c >> 3, colh = (c & 7) * 8; \
            size_t goff = (size_t)(b*TT + (kt0) + r)*QKVD + h*DHH + colh; \
            asm volatile("cp.async.cg.shared.global [%0], [%1], 16;\n" \
                :: "r"(smem_u32(&S.Kh[buf][r][colh])), "l"(g_qkv_h + goff + DD)); \
            asm volatile("cp.async.cg.shared.global [%0], [%1], 16;\n" \
                :: "r"(smem_u32(&S.Vh[buf][r][colh])), "l"(g_qkv_h + goff + 2*DD)); \
        } \
        if (tid < 127) \
            asm volatile("cp.async.ca.shared.global [%0], [%1], 4;\n" \
                :: "r"(smem_u32(&S.Sb[buf][tid])), \
                   "l"(g_biasrel + h*2048 + ((kt0) - q0 + 960) + tid)); \
        asm volatile("cp.async.commit_group;\n"); \
    } while (0)

    FA_LOAD_TILE(0, 0);   // prefetch tile 0 (overlaps Q fill)

    const __half2 qscale = __floats2half2_rn(0.125f, 0.125f);
    for (int i = tid; i < 64*16; i += 128) {
        int r = i >> 4, c4 = (i & 15) * 4;
        size_t off = (size_t)(b*TT + q0 + r)*QKVD + h*DHH + c4;
        __half2 a0 = *reinterpret_cast<const __half2*>(&g_qkv_h[off]);
        __half2 a1 = *reinterpret_cast<const __half2*>(&g_qkv_h[off+2]);
        *reinterpret_cast<__half2*>(&S.Qh[r][c4])   = __hmul2(a0, qscale);
        *reinterpret_cast<__half2*>(&S.Qh[r][c4+2]) = __hmul2(a1, qscale);
    }

    float o[8][4];
    #pragma unroll
    for (int n = 0; n < 8; n++)
        #pragma unroll
        for (int r = 0; r < 4; r++) o[n][r] = 0.f;
    float mrow[2] = { -3.0e38f, -3.0e38f };
    float lrow[2] = { 0.f, 0.f };

    for (int t = 0; t < TT/64; t++) {
        int kt0 = t * 64;
        int buf = t & 1;
        if (t + 1 < TT/64) FA_LOAD_TILE(buf ^ 1, kt0 + 64);
        else               asm volatile("cp.async.commit_group;\n");
        asm volatile("cp.async.wait_group 1;\n");
        __syncthreads();

        // ---- S = Q @ K^T ----
        float sacc[8][4];
        #pragma unroll
        for (int n = 0; n < 8; n++)
            #pragma unroll
            for (int r = 0; r < 4; r++) sacc[n][r] = 0.f;

        #pragma unroll
        for (int ks = 0; ks < 4; ks++) {
            int kc = ks*16 + (lane >> 4) * 8;
            unsigned aq[4];
            asm volatile("ldmatrix.sync.aligned.m8n8.x4.shared.b16 {%0,%1,%2,%3}, [%4];\n"
                : "=r"(aq[0]), "=r"(aq[1]), "=r"(aq[2]), "=r"(aq[3])
                : "r"(smem_u32(&S.Qh[wid*16 + (lane & 15)][kc])));
            unsigned bk[4][4];
            #pragma unroll
            for (int jb = 0; jb < 4; jb++) {
                asm volatile("ldmatrix.sync.aligned.m8n8.x4.shared.b16 {%0,%1,%2,%3}, [%4];\n"
                    : "=r"(bk[jb][0]), "=r"(bk[jb][1]), "=r"(bk[jb][2]), "=r"(bk[jb][3])
                    : "r"(smem_u32(&S.Kh[buf][jb*16 + (lane & 15)][kc])));
            }
            #pragma unroll
            for (int n8 = 0; n8 < 8; n8++) {
                int jb = n8 >> 1, p = n8 & 1;
                asm volatile(
                    "mma.sync.aligned.m16n8k16.row.col.f32.f16.f16.f32 "
                    "{%0,%1,%2,%3}, {%4,%5,%6,%7}, {%8,%9}, {%0,%1,%2,%3};\n"
                    : "+f"(sacc[n8][0]), "+f"(sacc[n8][1]), "+f"(sacc[n8][2]), "+f"(sacc[n8][3])
                    : "r"(aq[0]), "r"(aq[1]), "r"(aq[2]), "r"(aq[3]),
                      "r"(bk[jb][p]), "r"(bk[jb][p+2]));
            }
        }

        // ---- bias + bitmask + online softmax ----
        unsigned long long mm[2];
        #pragma unroll
        for (int e = 0; e < 2; e++) {
            int row = b*TT + q0 + qrel + e*8;
            unsigned w0 = g_maskbits[row*32 + (kt0 >> 5)];
            unsigned w1 = g_maskbits[row*32 + (kt0 >> 5) + 1];
            mm[e] = ((unsigned long long)w1 << 32) | w0;
        }
        float mnew[2] = { mrow[0], mrow[1] };
        #pragma unroll
        for (int n = 0; n < 8; n++) {
            #pragma unroll
            for (int e = 0; e < 2; e++) {
                int qr = qrel + e*8;
                #pragma unroll
                for (int c = 0; c < 2; c++) {
                    int kr = n*8 + 2*lk + c;
                    float s = sacc[n][e*2+c] + S.Sb[buf][kr - qr + 63];
                    if (!((mm[e] >> kr) & 1ull)) s = -1e9f;
                    sacc[n][e*2+c] = s;
                    mnew[e] = fmaxf(mnew[e], s);
                }
            }
        }
        #pragma unroll
        for (int e = 0; e < 2; e++) {
            mnew[e] = fmaxf(mnew[e], __shfl_xor_sync(0xffffffffu, mnew[e], 1));
            mnew[e] = fmaxf(mnew[e], __shfl_xor_sync(0xffffffffu, mnew[e], 2));
        }
        float alpha[2], rs[2] = {0.f, 0.f};
        alpha[0] = __expf(mrow[0] - mnew[0]);
        alpha[1] = __expf(mrow[1] - mnew[1]);
        mrow[0] = mnew[0]; mrow[1] = mnew[1];

        #pragma unroll
        for (int n = 0; n < 8; n++) {
            #pragma unroll
            for (int e = 0; e < 2; e++) {
                float p0 = __expf(sacc[n][e*2+0] - mnew[e]);
                float p1 = __expf(sacc[n][e*2+1] - mnew[e]);
                rs[e] += p0 + p1;
                *reinterpret_cast<__half2*>(&S.Ph[wid][lq + e*8][n*8 + 2*lk]) =
                    __floats2half2_rn(p0, p1);
            }
        }
        #pragma unroll
        for (int e = 0; e < 2; e++) {
            rs[e] += __shfl_xor_sync(0xffffffffu, rs[e], 1);
            rs[e] += __shfl_xor_sync(0xffffffffu, rs[e], 2);
            lrow[e] = lrow[e] * alpha[e] + rs[e];
        }
        #pragma unroll
        for (int n = 0; n < 8; n++) {
            o[n][0] *= alpha[0]; o[n][1] *= alpha[0];
            o[n][2] *= alpha[1]; o[n][3] *= alpha[1];
        }
        __syncwarp();

        // ---- O += P @ V ----
        #pragma unroll
        for (int ks = 0; ks < 4; ks++) {
            int kc = ks*16 + (lane >> 4) * 8;
            unsigned ap[4];
            asm volatile("ldmatrix.sync.aligned.m8n8.x4.shared.b16 {%0,%1,%2,%3}, [%4];\n"
                : "=r"(ap[0]), "=r"(ap[1]), "=r"(ap[2]), "=r"(ap[3])
                : "r"(smem_u32(&S.Ph[wid][lane & 15][kc])));
            int vrow = ks*16 + (lane & 7) + ((lane >> 3) & 1) * 8;
            unsigned bv[4][4];
            #pragma unroll
            for (int jb = 0; jb < 4; jb++) {
                int vcol = jb*16 + ((lane >> 4) & 1) * 8;
                asm volatile("ldmatrix.sync.aligned.m8n8.x4.trans.shared.b16 {%0,%1,%2,%3}, [%4];\n"
                    : "=r"(bv[jb][0]), "=r"(bv[jb][1]), "=r"(bv[jb][2]), "=r"(bv[jb][3])
                    : "r"(smem_u32(&S.Vh[buf][vrow][vcol])));
            }
            #pragma unroll
            for (int n8 = 0; n8 < 8; n8++) {
                int jb = n8 >> 1, q2 = n8 & 1;
                asm volatile(
                    "mma.sync.aligned.m16n8k16.row.col.f32.f16.f16.f32 "
                    "{%0,%1,%2,%3}, {%4,%5,%6,%7}, {%8,%9}, {%0,%1,%2,%3};\n"
                    : "+f"(o[n8][0]), "+f"(o[n8][1]), "+f"(o[n8][2]), "+f"(o[n8][3])
                    : "r"(ap[0]), "r"(ap[1]), "r"(ap[2]), "r"(ap[3]),
                      "r"(bv[jb][2*q2]), "r"(bv[jb][2*q2+1]));
            }
        }
        __syncthreads();   // compute done before next iter overwrites buf
    }
    #undef FA_LOAD_TILE

    float inv0 = 1.0f / lrow[0], inv1 = 1.0f / lrow[1];
    #pragma unroll
    for (int e = 0; e < 2; e++) {
        int qg = b*TT + q0 + qrel + e*8;
        float inv = e ? inv1 : inv0;
        #pragma unroll
        for (int n = 0; n < 8; n++) {
            __half2 hw = __floats2half2_rn(o[n][e*2+0] * inv, o[n][e*2+1] * inv);
            *reinterpret_cast<__half2*>(&g_ctx_h[(size_t)qg*DD + h*DHH + n*8 + 2*lk]) = hw;
        }
    }
}

// ---------------- host launcher ----------------
extern "C" void kernel_launch(void* const* d_in, const int* in_sizes, int n_in,
                              void* d_out, int out_size)
{
    const float* x       = (const float*)d_in[0];
    const int*   mask    = (const int*)  d_in[1];
    const float* cond    = (const float*)d_in[2];
    const float* norm1_w = (const float*)d_in[3];
    const float* f1gw    = (const float*)d_in[4];
    const float* f1gb    = (const float*)d_in[5];
    const float* f1bw    = (const float*)d_in[6];
    const float* f1bb    = (const float*)d_in[7];
    const float* wq      = (const float*)d_in[8];
    const float* wk      = (const float*)d_in[9];
    const float* wv      = (const float*)d_in[10];
    const float* wo      = (const float*)d_in[11];
    const float* rel_emb = (const float*)d_in[12];
    const float* norm3_w = (const float*)d_in[13];
    const float* f3gw    = (const float*)d_in[14];
    const float* f3gb    = (const float*)d_in[15];
    const float* f3bw    = (const float*)d_in[16];
    const float* f3bb    = (const float*)d_in[17];
    const float* w1      = (const float*)d_in[18];
    const float* w2      = (const float*)d_in[19];
    float* out = (float*)d_out;
    float* outbias = (out_size >= BTD + BIAS_ELEMS) ? out + BTD : nullptr;

    float *p_x1;
    float *p_g1, *p_b1, *p_g3, *p_b3;
    __half *p_y_h, *p_qkv_h, *p_ctx_h, *p_gg_h;
    __half *p_wqkvT, *p_woT, *p_w1T, *p_w2T;
    cudaGetSymbolAddress((void**)&p_g1, g_gamma1);
    cudaGetSymbolAddress((void**)&p_b1, g_beta1);
    cudaGetSymbolAddress((void**)&p_g3, g_gamma3);
    cudaGetSymbolAddress((void**)&p_b3, g_beta3);
    cudaGetSymbolAddress((void**)&p_x1, g_x1);
    cudaGetSymbolAddress((void**)&p_y_h,  g_y_h);
    cudaGetSymbolAddress((void**)&p_qkv_h, g_qkv_h);
    cudaGetSymbolAddress((void**)&p_ctx_h, g_ctx_h);
    cudaGetSymbolAddress((void**)&p_gg_h, g_gg_h);
    cudaGetSymbolAddress((void**)&p_wqkvT, g_wqkvT);
    cudaGetSymbolAddress((void**)&p_woT, g_woT);
    cudaGetSymbolAddress((void**)&p_w1T, g_w1T);
    cudaGetSymbolAddress((void**)&p_w2T, g_w2T);

    cudaFuncSetAttribute(flash_attn_kernel,
                         cudaFuncAttributeMaxDynamicSharedMemorySize,
                         (int)sizeof(FlashSmemH2));

    // 0) transposes + mask bits + FiLM + bias
    dim3 tb(32, 8);
    transpose_h_kernel<<<dim3(DD/32, DD/32), tb>>>(wq, p_wqkvT,           DD, DD, 0);
    transpose_h_kernel<<<dim3(DD/32, DD/32), tb>>>(wk, p_wqkvT + DD*DD,   DD, DD, 0);
    transpose_h_kernel<<<dim3(DD/32, DD/32), tb>>>(wv, p_wqkvT + 2*DD*DD, DD, DD, 0);
    transpose_h_kernel<<<dim3(DD/32, DD/32), tb>>>(wo, p_woT, DD, DD, 0);
    transpose_h_kernel<<<dim3(4*DD/32, DD/32), tb>>>(w1, p_w1T, DD, 4*DD, 1);
    transpose_h_kernel<<<dim3(DD/32, 2*DD/32), tb>>>(w2, p_w2T, 2*DD, DD, 0);
    maskbits_kernel<<<BT/8, 256>>>(mask);

    film_params_kernel<<<(BB*DD + 255)/256, 256>>>(cond, f1gw, f1gb, f1bw, f1bb,
                                                   f3gw, f3gb, f3bw, f3bb);
    biasrel_kernel<<<(2047 + 255)/256, 256>>>(rel_emb);
    if (outbias)
        bias_out_kernel<<<(TT*TT + 255)/256, 256>>>(rel_emb, outbias);

    // 2) y = film(rmsnorm(x)) -> half
    rmsnorm_film_kernel<<<BT, 256>>>(x, norm1_w, p_g1, p_b1, p_y_h);

    // 3) merged QKV projection (half packed output)
    gemm_f16_kernel<1><<<dim3(3*DD/GBN, BT/GBM), 128>>>(BT, 3*DD, DD, p_y_h, p_wqkvT,
                                                        nullptr, nullptr, p_qkv_h);

    // 4) fused flash attention -> half ctx
    flash_attn_kernel<<<dim3(TT/64, BB*HH), 128, sizeof(FlashSmemH2)>>>();

    // 5) output projection + residual -> x1 (fp32)
    gemm_f16_kernel<0><<<dim3(DD/GBN, BT/GBM), 128>>>(BT, DD, DD, p_ctx_h, p_woT,
                                                      x, p_x1, nullptr);

    // 6) y2 = film3(rmsnorm(x1)) -> half
    rmsnorm_film_kernel<<<BT, 256>>>(p_x1, norm3_w, p_g3, p_b3, p_y_h);

    // 7) FFN: fused ffn1+geglu -> half gg ; ffn2 + residual -> out
    gemm_f16_kernel<2><<<dim3(4*DD/GBN, BT/GBM), 128>>>(BT, 4*DD, DD, p_y_h, p_w1T,
                                                        nullptr, nullptr, p_gg_h);
    gemm_f16_kernel<0><<<dim3(DD/GBN, BT/GBM), 128>>>(BT, DD, 2*DD, p_gg_h, p_w2T,
                                                      p_x1, out, nullptr);
}

// round 17
// speedup vs baseline: 1.2770x; 1.0529x over previous
#include <cuda_runtime.h>
#include <cuda_fp16.h>
#include <math.h>

#define BB 4
#define TT 1024
#define DD 1024
#define HH 16
#define DHH 64
#define DCC 64
#define BT (BB*TT)        // 4096
#define BTD (BB*TT*DD)    // 4194304
#define BIAS_ELEMS (HH*TT*TT) // 16777216

// ---------------- scratch (device globals; no allocation) ----------------
__device__ float g_gamma1[BB*DD];
__device__ float g_beta1 [BB*DD];
__device__ float g_gamma3[BB*DD];
__device__ float g_beta3 [BB*DD];
__device__ float g_x1  [BTD];
__device__ float g_biasrel[HH*2048];
__device__ unsigned g_maskbits[BT*32];
// fp16 activation/weight buffers
__device__ __half g_y_h  [BTD];
__device__ __half g_qkv_h[(size_t)BT*3*DD];
__device__ __half g_ctx_h[BTD];
__device__ __half g_gg_h [(size_t)BT*2*DD];
__device__ __half g_wqkvT[(size_t)3*DD*DD];
__device__ __half g_woT[DD*DD];
__device__ __half g_w1T[(size_t)4*DD*DD];     // geglu-permuted rows
__device__ __half g_w2T[(size_t)2*DD*DD];

__device__ __forceinline__ unsigned smem_u32(const void* p) {
    return (unsigned)__cvta_generic_to_shared(p);
}

// ---------------- T5 bucket ----------------
__device__ __forceinline__ int t5_bucket(int rp) {
    int bucket = (rp > 0) ? 16 : 0;
    int arp = rp < 0 ? -rp : rp;
    int off;
    if (arp < 8) {
        off = arp;
    } else {
        float l = logf((float)arp * 0.125f) / logf(16.0f) * 8.0f;
        off = 8 + (int)l;
        if (off > 15) off = 15;
    }
    return bucket + off;
}

// ---------------- batched weight transpose -> half K-major (6 jobs, 1 launch) ----------------
// job j: src[k][n] -> dst[n'][k] with optional geglu permute
struct TransJobs {
    const float* src[6];
    __half* dst[6];
    int Kd[6], Nd[6], mode[6], blk0[7], nx[6];
};

__global__ void transpose_all_kernel(TransJobs jobs)
{
    __shared__ float ts[32][33];
    int bid = blockIdx.x;
    int j = 0;
    #pragma unroll
    for (int t = 0; t < 6; t++)
        if (bid >= jobs.blk0[t+1]) j = t+1;
    int local = bid - jobs.blk0[j];
    int nx = jobs.nx[j];
    int n0 = (local % nx) * 32, k0 = (local / nx) * 32;
    const float* src = jobs.src[j];
    __half* dst = jobs.dst[j];
    int Kd = jobs.Kd[j], Nd = jobs.Nd[j], mode = jobs.mode[j];

    int tx = threadIdx.x, ty = threadIdx.y;   // 32 x 8
    #pragma unroll
    for (int i = 0; i < 32; i += 8)
        ts[ty+i][tx] = src[(size_t)(k0+ty+i)*Nd + n0+tx];
    __syncthreads();
    int half = Nd >> 1;
    #pragma unroll
    for (int i = 0; i < 32; i += 8) {
        int n = n0 + ty + i;
        int nd = (mode == 1) ? ((n < half) ? 2*n : 2*(n - half) + 1) : n;
        dst[(size_t)nd*Kd + k0+tx] = __float2half_rn(ts[tx][ty+i]);
    }
}

// ---------------- prologue: film params + bias LUT + maskbits in ONE launch ----------------
// blocks [0,16): film (4096 elems); [16,24): biasrel (2047); [24, 24+512): maskbits
#define PRO_FILM_BLKS 16
#define PRO_BIAS_BLKS 8
#define PRO_MASK_BLKS (BT/8)

__global__ void prologue_kernel(const float* __restrict__ cond,
    const float* __restrict__ g1w, const float* __restrict__ g1b,
    const float* __restrict__ b1w, const float* __restrict__ b1b,
    const float* __restrict__ g3w, const float* __restrict__ g3b,
    const float* __restrict__ b3w, const float* __restrict__ b3b,
    const float* __restrict__ rel_emb, const int* __restrict__ mask)
{
    int blk = blockIdx.x;
    if (blk < PRO_FILM_BLKS) {
        int idx = blk * 256 + threadIdx.x;
        if (idx >= BB*DD) return;
        int b = idx / DD, d = idx % DD;
        float s1 = 0.f, s2 = 0.f, s3 = 0.f, s4 = 0.f;
        #pragma unroll 8
        for (int c = 0; c < DCC; c++) {
            float cv = cond[b*DCC + c];
            s1 += cv * g1w[c*DD + d];
            s2 += cv * b1w[c*DD + d];
            s3 += cv * g3w[c*DD + d];
            s4 += cv * b3w[c*DD + d];
        }
        g_gamma1[idx] = s1 + g1b[d];
        g_beta1 [idx] = s2 + b1b[d];
        g_gamma3[idx] = s3 + g3b[d];
        g_beta3 [idx] = s4 + b3b[d];
    } else if (blk < PRO_FILM_BLKS + PRO_BIAS_BLKS) {
        int idx = (blk - PRO_FILM_BLKS) * 256 + threadIdx.x;
        if (idx >= 2047) return;
        int bucket = t5_bucket(idx - 1023);
        #pragma unroll
        for (int h = 0; h < HH; h++)
            g_biasrel[h*2048 + idx] = rel_emb[bucket*HH + h];
    } else {
        int base = blk - PRO_FILM_BLKS - PRO_BIAS_BLKS;
        int warp = base * 8 + (threadIdx.x >> 5);
        int lane = threadIdx.x & 31;
        if (warp >= BT) return;
        const int* mrow = mask + (size_t)warp * TT;
        #pragma unroll 4
        for (int w = 0; w < 32; w++) {
            unsigned word = __ballot_sync(0xffffffffu, mrow[w*32 + lane] != 0);
            if (lane == 0) g_maskbits[warp*32 + w] = word;
        }
    }
}

// ---------------- bias output tensor [1,H,T,T] ----------------
__global__ void bias_out_kernel(const float* __restrict__ rel_emb, float* __restrict__ outbias)
{
    int idx = blockIdx.x * blockDim.x + threadIdx.x;
    if (idx >= TT*TT) return;
    int q = idx / TT, k = idx % TT;
    int bucket = t5_bucket(k - q);
    #pragma unroll
    for (int h = 0; h < HH; h++)
        outbias[(size_t)h*TT*TT + idx] = rel_emb[bucket*HH + h];
}

// ---------------- RMSNorm + FiLM (warp-shuffle reduce) ----------------
__global__ void rmsnorm_film_kernel(const float* __restrict__ x, const float* __restrict__ w,
                                    const float* __restrict__ gamma, const float* __restrict__ beta,
                                    __half* __restrict__ y)
{
    int row = blockIdx.x;
    int b = row / TT;
    const float* xr = x + (size_t)row * DD;
    __half* yr = y + (size_t)row * DD;
    int d4 = threadIdx.x * 4;
    float4 v = *reinterpret_cast<const float4*>(&xr[d4]);
    float s = v.x*v.x + v.y*v.y + v.z*v.z + v.w*v.w;
    #pragma unroll
    for (int o = 16; o > 0; o >>= 1)
        s += __shfl_xor_sync(0xffffffffu, s, o);
    __shared__ float wred[8];
    if ((threadIdx.x & 31) == 0) wred[threadIdx.x >> 5] = s;
    __syncthreads();
    float tot = 0.f;
    #pragma unroll
    for (int i = 0; i < 8; i++) tot += wred[i];
    float rs = rsqrtf(tot * (1.0f/DD) + 1e-6f);
    float4 wv = *reinterpret_cast<const float4*>(&w[d4]);
    float4 gv = *reinterpret_cast<const float4*>(&gamma[b*DD + d4]);
    float4 bv = *reinterpret_cast<const float4*>(&beta[b*DD + d4]);
    __half2 h0 = __floats2half2_rn(wv.x * v.x * rs * (gv.x + 1.0f) + bv.x,
                                   wv.y * v.y * rs * (gv.y + 1.0f) + bv.y);
    __half2 h1 = __floats2half2_rn(wv.z * v.z * rs * (gv.z + 1.0f) + bv.z,
                                   wv.w * v.w * rs * (gv.w + 1.0f) + bv.w);
    *reinterpret_cast<__half2*>(&yr[d4])   = h0;
    *reinterpret_cast<__half2*>(&yr[d4+2]) = h1;
}

// ---------------- FP16 GEMM 64x128 tile, 128 threads, 3-stage cp.async ----------------
// OUT_MODE 0: C fp32 (+Res) ; 1: Ch half ; 2: Ch half geglu
#define GBM 64
#define GBN 128
#define GBK 32
#define HPAD 8

template<int OUT_MODE>
__global__ __launch_bounds__(128) void gemm_f16_kernel(int M, int N, int K,
    const __half* __restrict__ A, const __half* __restrict__ Bt,
    const float* __restrict__ Res, float* __restrict__ C, __half* __restrict__ Ch)
{
    __shared__ __half As[3][GBM][GBK+HPAD];
    __shared__ __half Bs[3][GBN][GBK+HPAD];

    int tid = threadIdx.x;
    int wid = tid >> 5, lane = tid & 31;
    int wn = wid;

    const __half* Ag = A  + (size_t)blockIdx.y * GBM * K;
    const __half* Bg = Bt + (size_t)blockIdx.x * GBN * K;

    float acc[4][4][4];
    #pragma unroll
    for (int i = 0; i < 4; i++)
        #pragma unroll
        for (int j = 0; j < 4; j++)
            #pragma unroll
            for (int r = 0; r < 4; r++) acc[i][j][r] = 0.f;

    int lr = tid >> 2, lc = (tid & 3) * 8;

    #define LOAD_STAGE(buf, kt) do { \
        asm volatile("cp.async.cg.shared.global [%0], [%1], 16;\n" \
            :: "r"(smem_u32(&As[buf][lr][lc])),    "l"(Ag + (size_t)lr*K + (kt) + lc)); \
        asm volatile("cp.async.cg.shared.global [%0], [%1], 16;\n" \
            :: "r"(smem_u32(&As[buf][lr+32][lc])), "l"(Ag + (size_t)(lr+32)*K + (kt) + lc)); \
        asm volatile("cp.async.cg.shared.global [%0], [%1], 16;\n" \
            :: "r"(smem_u32(&Bs[buf][lr][lc])),    "l"(Bg + (size_t)lr*K + (kt) + lc)); \
        asm volatile("cp.async.cg.shared.global [%0], [%1], 16;\n" \
            :: "r"(smem_u32(&Bs[buf][lr+32][lc])), "l"(Bg + (size_t)(lr+32)*K + (kt) + lc)); \
        asm volatile("cp.async.cg.shared.global [%0], [%1], 16;\n" \
            :: "r"(smem_u32(&Bs[buf][lr+64][lc])), "l"(Bg + (size_t)(lr+64)*K + (kt) + lc)); \
        asm volatile("cp.async.cg.shared.global [%0], [%1], 16;\n" \
            :: "r"(smem_u32(&Bs[buf][lr+96][lc])), "l"(Bg + (size_t)(lr+96)*K + (kt) + lc)); \
        asm volatile("cp.async.commit_group;\n"); \
    } while (0)

    int nk = K / GBK;
    LOAD_STAGE(0, 0);
    LOAD_STAGE(1, GBK);

    int bufc = 0;
    for (int t = 0; t < nk; t++) {
        int bufn = bufc + 2; if (bufn >= 3) bufn -= 3;
        if (t + 2 < nk) LOAD_STAGE(bufn, (t+2) * GBK);
        else            asm volatile("cp.async.commit_group;\n");
        asm volatile("cp.async.wait_group 2;\n");
        __syncthreads();

        #pragma unroll
        for (int kk = 0; kk < 2; kk++) {
            int k0 = kk * 16;
            int kc = k0 + (lane >> 4) * 8;
            unsigned af[4][4];
            unsigned bf[2][4];
            #pragma unroll
            for (int i = 0; i < 4; i++) {
                int m = i*16 + (lane & 15);
                asm volatile("ldmatrix.sync.aligned.m8n8.x4.shared.b16 {%0,%1,%2,%3}, [%4];\n"
                    : "=r"(af[i][0]), "=r"(af[i][1]), "=r"(af[i][2]), "=r"(af[i][3])
                    : "r"(smem_u32(&As[bufc][m][kc])));
            }
            #pragma unroll
            for (int jb = 0; jb < 2; jb++) {
                int n = wn*32 + jb*16 + (lane & 15);
                asm volatile("ldmatrix.sync.aligned.m8n8.x4.shared.b16 {%0,%1,%2,%3}, [%4];\n"
                    : "=r"(bf[jb][0]), "=r"(bf[jb][1]), "=r"(bf[jb][2]), "=r"(bf[jb][3])
                    : "r"(smem_u32(&Bs[bufc][n][kc])));
            }
            #pragma unroll
            for (int i = 0; i < 4; i++)
                #pragma unroll
                for (int j = 0; j < 4; j++) {
                    int jb = j >> 1, p = j & 1;
                    asm volatile(
                        "mma.sync.aligned.m16n8k16.row.col.f32.f16.f16.f32 "
                        "{%0,%1,%2,%3}, {%4,%5,%6,%7}, {%8,%9}, {%0,%1,%2,%3};\n"
                        : "+f"(acc[i][j][0]), "+f"(acc[i][j][1]), "+f"(acc[i][j][2]), "+f"(acc[i][j][3])
                        : "r"(af[i][0]), "r"(af[i][1]), "r"(af[i][2]), "r"(af[i][3]),
                          "r"(bf[jb][p]), "r"(bf[jb][p+2]));
                }
        }
        __syncthreads();
        bufc = bufc + 1; if (bufc >= 3) bufc -= 3;
    }
    #undef LOAD_STAGE

    if (OUT_MODE == 2) {
        int Ng = N >> 1;
        __half* Cg = Ch + (size_t)blockIdx.y * GBM * Ng + blockIdx.x * (GBN >> 1);
        #pragma unroll
        for (int i = 0; i < 4; i++) {
            int r0 = i*16 + (lane >> 2);
            int r1 = r0 + 8;
            #pragma unroll
            for (int j = 0; j < 4; j++) {
                int gc = (wn*32 + j*8 + (lane & 3) * 2) >> 1;
                float p1a = acc[i][j][0], p2a = acc[i][j][1];
                float p1b = acc[i][j][2], p2b = acc[i][j][3];
                float ga = 0.5f * p2a * (1.0f + erff(p2a * 0.70710678118654752f));
                float gb = 0.5f * p2b * (1.0f + erff(p2b * 0.70710678118654752f));
                Cg[(size_t)r0*Ng + gc] = __float2half_rn(p1a * ga);
                Cg[(size_t)r1*Ng + gc] = __float2half_rn(p1b * gb);
            }
        }
    } else if (OUT_MODE == 1) {
        __half* Cg = Ch + (size_t)blockIdx.y * GBM * N + blockIdx.x * GBN;
        #pragma unroll
        for (int i = 0; i < 4; i++) {
            int r0 = i*16 + (lane >> 2);
            int r1 = r0 + 8;
            #pragma unroll
            for (int j = 0; j < 4; j++) {
                int c0 = wn*32 + j*8 + (lane & 3) * 2;
                *reinterpret_cast<__half2*>(&Cg[(size_t)r0*N + c0]) =
                    __floats2half2_rn(acc[i][j][0], acc[i][j][1]);
                *reinterpret_cast<__half2*>(&Cg[(size_t)r1*N + c0]) =
                    __floats2half2_rn(acc[i][j][2], acc[i][j][3]);
            }
        }
    } else {
        float* Cg = C + (size_t)blockIdx.y * GBM * N + blockIdx.x * GBN;
        const float* Rg = Res ? Res + (size_t)blockIdx.y * GBM * N + blockIdx.x * GBN : nullptr;
        #pragma unroll
        for (int i = 0; i < 4; i++) {
            int r0 = i*16 + (lane >> 2);
            int r1 = r0 + 8;
            #pragma unroll
            for (int j = 0; j < 4; j++) {
                int c0 = wn*32 + j*8 + (lane & 3) * 2;
                float v0 = acc[i][j][0], v1 = acc[i][j][1];
                float v2 = acc[i][j][2], v3 = acc[i][j][3];
                if (Rg) {
                    v0 += Rg[(size_t)r0*N + c0];   v1 += Rg[(size_t)r0*N + c0+1];
                    v2 += Rg[(size_t)r1*N + c0];   v3 += Rg[(size_t)r1*N + c0+1];
                }
                Cg[(size_t)r0*N + c0]   = v0;  Cg[(size_t)r0*N + c0+1] = v1;
                Cg[(size_t)r1*N + c0]   = v2;  Cg[(size_t)r1*N + c0+1] = v3;
            }
        }
    }
}

// ---------------- fused flash attention (fp16 mma k16, double-buffered cp.async) ----------------
#define FPITCH 72
#define QKVD (3*DD)

struct FlashSmemH2 {
    __half Qh[64][FPITCH];
    __half Kh[2][64][FPITCH];
    __half Vh[2][64][FPITCH];
    __half Ph[4][16][FPITCH];
    float  Sb[2][128];
};

__global__ __launch_bounds__(128) void flash_attn_kernel()
{
    extern __shared__ char fa_raw[];
    FlashSmemH2& S = *reinterpret_cast<FlashSmemH2*>(fa_raw);

    int qt = blockIdx.x, bh = blockIdx.y;
    int b = bh / HH, h = bh % HH;
    int q0 = qt * 64;
    int tid = threadIdx.x, wid = tid >> 5, lane = tid & 31;
    int lq = lane >> 2, lk = lane & 3;
    int qrel = wid*16 + lq;

    #define FA_LOAD_TILE(buf, kt0) do { \
        _Pragma("unroll") \
        for (int j = 0; j < 4; j++) { \
            int c = tid + j*128; \
            int r = c >> 3, colh = (c & 7) * 8; \
            size_t goff = (size_t)(b*TT + (kt0) + r)*QKVD + h*DHH + colh; \
            asm volatile("cp.async.cg.shared.global [%0], [%1], 16;\n" \
                :: "r"(smem_u32(&S.Kh[buf][r][colh])), "l"(g_qkv_h + goff + DD)); \
            asm volatile("cp.async.cg.shared.global [%0], [%1], 16;\n" \
                :: "r"(smem_u32(&S.Vh[buf][r][colh])), "l"(g_qkv_h + goff + 2*DD)); \
        } \
        if (tid < 127) \
            asm volatile("cp.async.ca.shared.global [%0], [%1], 4;\n" \
                :: "r"(smem_u32(&S.Sb[buf][tid])), \
                   "l"(g_biasrel + h*2048 + ((kt0) - q0 + 960) + tid)); \
        asm volatile("cp.async.commit_group;\n"); \
    } while (0)

    FA_LOAD_TILE(0, 0);

    const __half2 qscale = __floats2half2_rn(0.125f, 0.125f);
    for (int i = tid; i < 64*16; i += 128) {
        int r = i >> 4, c4 = (i & 15) * 4;
        size_t off = (size_t)(b*TT + q0 + r)*QKVD + h*DHH + c4;
        __half2 a0 = *reinterpret_cast<const __half2*>(&g_qkv_h[off]);
        __half2 a1 = *reinterpret_cast<const __half2*>(&g_qkv_h[off+2]);
        *reinterpret_cast<__half2*>(&S.Qh[r][c4])   = __hmul2(a0, qscale);
        *reinterpret_cast<__half2*>(&S.Qh[r][c4+2]) = __hmul2(a1, qscale);
    }

    float o[8][4];
    #pragma unroll
    for (int n = 0; n < 8; n++)
        #pragma unroll
        for (int r = 0; r < 4; r++) o[n][r] = 0.f;
    float mrow[2] = { -3.0e38f, -3.0e38f };
    float lrow[2] = { 0.f, 0.f };

    for (int t = 0; t < TT/64; t++) {
        int kt0 = t * 64;
        int buf = t & 1;
        if (t + 1 < TT/64) FA_LOAD_TILE(buf ^ 1, kt0 + 64);
        else               asm volatile("cp.async.commit_group;\n");
        asm volatile("cp.async.wait_group 1;\n");
        __syncthreads();

        float sacc[8][4];
        #pragma unroll
        for (int n = 0; n < 8; n++)
            #pragma unroll
            for (int r = 0; r < 4; r++) sacc[n][r] = 0.f;

        #pragma unroll
        for (int ks = 0; ks < 4; ks++) {
            int kc = ks*16 + (lane >> 4) * 8;
            unsigned aq[4];
            asm volatile("ldmatrix.sync.aligned.m8n8.x4.shared.b16 {%0,%1,%2,%3}, [%4];\n"
                : "=r"(aq[0]), "=r"(aq[1]), "=r"(aq[2]), "=r"(aq[3])
                : "r"(smem_u32(&S.Qh[wid*16 + (lane & 15)][kc])));
            unsigned bk[4][4];
            #pragma unroll
            for (int jb = 0; jb < 4; jb++) {
                asm volatile("ldmatrix.sync.aligned.m8n8.x4.shared.b16 {%0,%1,%2,%3}, [%4];\n"
                    : "=r"(bk[jb][0]), "=r"(bk[jb][1]), "=r"(bk[jb][2]), "=r"(bk[jb][3])
                    : "r"(smem_u32(&S.Kh[buf][jb*16 + (lane & 15)][kc])));
            }
            #pragma unroll
            for (int n8 = 0; n8 < 8; n8++) {
                int jb = n8 >> 1, p = n8 & 1;
                asm volatile(
                    "mma.sync.aligned.m16n8k16.row.col.f32.f16.f16.f32 "
                    "{%0,%1,%2,%3}, {%4,%5,%6,%7}, {%8,%9}, {%0,%1,%2,%3};\n"
                    : "+f"(sacc[n8][0]), "+f"(sacc[n8][1]), "+f"(sacc[n8][2]), "+f"(sacc[n8][3])
                    : "r"(aq[0]), "r"(aq[1]), "r"(aq[2]), "r"(aq[3]),
                      "r"(bk[jb][p]), "r"(bk[jb][p+2]));
            }
        }

        unsigned long long mm[2];
        #pragma unroll
        for (int e = 0; e < 2; e++) {
            int row = b*TT + q0 + qrel + e*8;
            unsigned w0 = g_maskbits[row*32 + (kt0 >> 5)];
            unsigned w1 = g_maskbits[row*32 + (kt0 >> 5) + 1];
            mm[e] = ((unsigned long long)w1 << 32) | w0;
        }
        float mnew[2] = { mrow[0], mrow[1] };
        #pragma unroll
        for (int n = 0; n < 8; n++) {
            #pragma unroll
            for (int e = 0; e < 2; e++) {
                int qr = qrel + e*8;
                #pragma unroll
                for (int c = 0; c < 2; c++) {
                    int kr = n*8 + 2*lk + c;
                    float s = sacc[n][e*2+c] + S.Sb[buf][kr - qr + 63];
                    if (!((mm[e] >> kr) & 1ull)) s = -1e9f;
                    sacc[n][e*2+c] = s;
                    mnew[e] = fmaxf(mnew[e], s);
                }
            }
        }
        #pragma unroll
        for (int e = 0; e < 2; e++) {
            mnew[e] = fmaxf(mnew[e], __shfl_xor_sync(0xffffffffu, mnew[e], 1));
            mnew[e] = fmaxf(mnew[e], __shfl_xor_sync(0xffffffffu, mnew[e], 2));
        }
        float alpha[2], rs[2] = {0.f, 0.f};
        alpha[0] = __expf(mrow[0] - mnew[0]);
        alpha[1] = __expf(mrow[1] - mnew[1]);
        mrow[0] = mnew[0]; mrow[1] = mnew[1];

        #pragma unroll
        for (int n = 0; n < 8; n++) {
            #pragma unroll
            for (int e = 0; e < 2; e++) {
                float p0 = __expf(sacc[n][e*2+0] - mnew[e]);
                float p1 = __expf(sacc[n][e*2+1] - mnew[e]);
                rs[e] += p0 + p1;
                *reinterpret_cast<__half2*>(&S.Ph[wid][lq + e*8][n*8 + 2*lk]) =
                    __floats2half2_rn(p0, p1);
            }
        }
        #pragma unroll
        for (int e = 0; e < 2; e++) {
            rs[e] += __shfl_xor_sync(0xffffffffu, rs[e], 1);
            rs[e] += __shfl_xor_sync(0xffffffffu, rs[e], 2);
            lrow[e] = lrow[e] * alpha[e] + rs[e];
        }
        #pragma unroll
        for (int n = 0; n < 8; n++) {
            o[n][0] *= alpha[0]; o[n][1] *= alpha[0];
            o[n][2] *= alpha[1]; o[n][3] *= alpha[1];
        }
        __syncwarp();

        #pragma unroll
        for (int ks = 0; ks < 4; ks++) {
            int kc = ks*16 + (lane >> 4) * 8;
            unsigned ap[4];
            asm volatile("ldmatrix.sync.aligned.m8n8.x4.shared.b16 {%0,%1,%2,%3}, [%4];\n"
                : "=r"(ap[0]), "=r"(ap[1]), "=r"(ap[2]), "=r"(ap[3])
                : "r"(smem_u32(&S.Ph[wid][lane & 15][kc])));
            int vrow = ks*16 + (lane & 7) + ((lane >> 3) & 1) * 8;
            unsigned bv[4][4];
            #pragma unroll
            for (int jb = 0; jb < 4; jb++) {
                int vcol = jb*16 + ((lane >> 4) & 1) * 8;
                asm volatile("ldmatrix.sync.aligned.m8n8.x4.trans.shared.b16 {%0,%1,%2,%3}, [%4];\n"
                    : "=r"(bv[jb][0]), "=r"(bv[jb][1]), "=r"(bv[jb][2]), "=r"(bv[jb][3])
                    : "r"(smem_u32(&S.Vh[buf][vrow][vcol])));
            }
            #pragma unroll
            for (int n8 = 0; n8 < 8; n8++) {
                int jb = n8 >> 1, q2 = n8 & 1;
                asm volatile(
                    "mma.sync.aligned.m16n8k16.row.col.f32.f16.f16.f32 "
                    "{%0,%1,%2,%3}, {%4,%5,%6,%7}, {%8,%9}, {%0,%1,%2,%3};\n"
                    : "+f"(o[n8][0]), "+f"(o[n8][1]), "+f"(o[n8][2]), "+f"(o[n8][3])
                    : "r"(ap[0]), "r"(ap[1]), "r"(ap[2]), "r"(ap[3]),
                      "r"(bv[jb][2*q2]), "r"(bv[jb][2*q2+1]));
            }
        }
        __syncthreads();
    }
    #undef FA_LOAD_TILE

    float inv0 = 1.0f / lrow[0], inv1 = 1.0f / lrow[1];
    #pragma unroll
    for (int e = 0; e < 2; e++) {
        int qg = b*TT + q0 + qrel + e*8;
        float inv = e ? inv1 : inv0;
        #pragma unroll
        for (int n = 0; n < 8; n++) {
            __half2 hw = __floats2half2_rn(o[n][e*2+0] * inv, o[n][e*2+1] * inv);
            *reinterpret_cast<__half2*>(&g_ctx_h[(size_t)qg*DD + h*DHH + n*8 + 2*lk]) = hw;
        }
    }
}

// ---------------- host launcher ----------------
extern "C" void kernel_launch(void* const* d_in, const int* in_sizes, int n_in,
                              void* d_out, int out_size)
{
    const float* x       = (const float*)d_in[0];
    const int*   mask    = (const int*)  d_in[1];
    const float* cond    = (const float*)d_in[2];
    const float* norm1_w = (const float*)d_in[3];
    const float* f1gw    = (const float*)d_in[4];
    const float* f1gb    = (const float*)d_in[5];
    const float* f1bw    = (const float*)d_in[6];
    const float* f1bb    = (const float*)d_in[7];
    const float* wq      = (const float*)d_in[8];
    const float* wk      = (const float*)d_in[9];
    const float* wv      = (const float*)d_in[10];
    const float* wo      = (const float*)d_in[11];
    const float* rel_emb = (const float*)d_in[12];
    const float* norm3_w = (const float*)d_in[13];
    const float* f3gw    = (const float*)d_in[14];
    const float* f3gb    = (const float*)d_in[15];
    const float* f3bw    = (const float*)d_in[16];
    const float* f3bb    = (const float*)d_in[17];
    const float* w1      = (const float*)d_in[18];
    const float* w2      = (const float*)d_in[19];
    float* out = (float*)d_out;
    float* outbias = (out_size >= BTD + BIAS_ELEMS) ? out + BTD : nullptr;

    float *p_x1;
    float *p_g1, *p_b1, *p_g3, *p_b3;
    __half *p_y_h, *p_qkv_h, *p_ctx_h, *p_gg_h;
    __half *p_wqkvT, *p_woT, *p_w1T, *p_w2T;
    cudaGetSymbolAddress((void**)&p_g1, g_gamma1);
    cudaGetSymbolAddress((void**)&p_b1, g_beta1);
    cudaGetSymbolAddress((void**)&p_g3, g_gamma3);
    cudaGetSymbolAddress((void**)&p_b3, g_beta3);
    cudaGetSymbolAddress((void**)&p_x1, g_x1);
    cudaGetSymbolAddress((void**)&p_y_h,  g_y_h);
    cudaGetSymbolAddress((void**)&p_qkv_h, g_qkv_h);
    cudaGetSymbolAddress((void**)&p_ctx_h, g_ctx_h);
    cudaGetSymbolAddress((void**)&p_gg_h, g_gg_h);
    cudaGetSymbolAddress((void**)&p_wqkvT, g_wqkvT);
    cudaGetSymbolAddress((void**)&p_woT, g_woT);
    cudaGetSymbolAddress((void**)&p_w1T, g_w1T);
    cudaGetSymbolAddress((void**)&p_w2T, g_w2T);

    cudaFuncSetAttribute(flash_attn_kernel,
                         cudaFuncAttributeMaxDynamicSharedMemorySize,
                         (int)sizeof(FlashSmemH2));

    // 0) single batched transpose launch (6 jobs)
    TransJobs tj;
    tj.src[0] = wq;  tj.dst[0] = p_wqkvT;            tj.Kd[0] = DD;   tj.Nd[0] = DD;   tj.mode[0] = 0; tj.nx[0] = DD/32;
    tj.src[1] = wk;  tj.dst[1] = p_wqkvT + DD*DD;    tj.Kd[1] = DD;   tj.Nd[1] = DD;   tj.mode[1] = 0; tj.nx[1] = DD/32;
    tj.src[2] = wv;  tj.dst[2] = p_wqkvT + 2*DD*DD;  tj.Kd[2] = DD;   tj.Nd[2] = DD;   tj.mode[2] = 0; tj.nx[2] = DD/32;
    tj.src[3] = wo;  tj.dst[3] = p_woT;              tj.Kd[3] = DD;   tj.Nd[3] = DD;   tj.mode[3] = 0; tj.nx[3] = DD/32;
    tj.src[4] = w1;  tj.dst[4] = p_w1T;              tj.Kd[4] = DD;   tj.Nd[4] = 4*DD; tj.mode[4] = 1; tj.nx[4] = 4*DD/32;
    tj.src[5] = w2;  tj.dst[5] = p_w2T;              tj.Kd[5] = 2*DD; tj.Nd[5] = DD;   tj.mode[5] = 0; tj.nx[5] = DD/32;
    int nb = 0;
    for (int j = 0; j < 6; j++) {
        tj.blk0[j] = nb;
        nb += tj.nx[j] * (tj.Kd[j] / 32);
    }
    tj.blk0[6] = nb;
    transpose_all_kernel<<<nb, dim3(32, 8)>>>(tj);

    // 1) fused prologue: film params + bias LUT + maskbits
    prologue_kernel<<<PRO_FILM_BLKS + PRO_BIAS_BLKS + PRO_MASK_BLKS, 256>>>(
        cond, f1gw, f1gb, f1bw, f1bb, f3gw, f3gb, f3bw, f3bb, rel_emb, mask);
    if (outbias)
        bias_out_kernel<<<(TT*TT + 255)/256, 256>>>(rel_emb, outbias);

    // 2) y = film(rmsnorm(x)) -> half
    rmsnorm_film_kernel<<<BT, 256>>>(x, norm1_w, p_g1, p_b1, p_y_h);

    // 3) merged QKV projection (half packed output)
    gemm_f16_kernel<1><<<dim3(3*DD/GBN, BT/GBM), 128>>>(BT, 3*DD, DD, p_y_h, p_wqkvT,
                                                        nullptr, nullptr, p_qkv_h);

    // 4) fused flash attention -> half ctx
    flash_attn_kernel<<<dim3(TT/64, BB*HH), 128, sizeof(FlashSmemH2)>>>();

    // 5) output projection + residual -> x1 (fp32)
    gemm_f16_kernel<0><<<dim3(DD/GBN, BT/GBM), 128>>>(BT, DD, DD, p_ctx_h, p_woT,
                                                      x, p_x1, nullptr);

    // 6) y2 = film3(rmsnorm(x1)) -> half
    rmsnorm_film_kernel<<<BT, 256>>>(p_x1, norm3_w, p_g3, p_b3, p_y_h);

    // 7) FFN: fused ffn1+geglu -> half gg ; ffn2 + residual -> out
    gemm_f16_kernel<2><<<dim3(4*DD/GBN, BT/GBM), 128>>>(BT, 4*DD, DD, p_y_h, p_w1T,
                                                        nullptr, nullptr, p_gg_h);
    gemm_f16_kernel<0><<<dim3(DD/GBN, BT/GBM), 128>>>(BT, DD, 2*DD, p_gg_h, p_w2T,
                                                      p_x1, out, nullptr);
}